// round 1
// baseline (speedup 1.0000x reference)
#include <cuda_runtime.h>
#include <cstdint>

#define NMAX 100000
#define EMAX 1600000
#define HD   256      // concat hidden dim (2*128)
#define NCLS 40

// ---------------- scratch (static device globals; no allocation) -------------
__device__ int   g_deg[NMAX];
__device__ int   g_rowptr[NMAX + 1];
__device__ int   g_cursor[NMAX];
__device__ int   g_esrc[EMAX];
__device__ float g_neigh[(size_t)NMAX * HD];
__device__ float g_h1[(size_t)NMAX * HD];
__device__ float g_h2[(size_t)NMAX * HD];

// ---------------- CSR build --------------------------------------------------
__global__ void zero_deg_kernel(int n) {
    int i = blockIdx.x * blockDim.x + threadIdx.x;
    if (i < n) g_deg[i] = 0;
}

__global__ void count_kernel(const int* __restrict__ dst, int e) {
    int i = blockIdx.x * blockDim.x + threadIdx.x;
    if (i < e) atomicAdd(&g_deg[dst[i]], 1);
}

// single-block exclusive scan of g_deg -> g_rowptr (+ copy into g_cursor)
__global__ void scan_kernel(int n) {
    __shared__ int wsums[32];
    __shared__ int s_carry;
    int t = threadIdx.x, lane = t & 31, wid = t >> 5;
    if (t == 0) s_carry = 0;
    __syncthreads();
    for (int base = 0; base < n; base += 1024) {
        int i = base + t;
        int v = (i < n) ? g_deg[i] : 0;
        int val = v;
#pragma unroll
        for (int off = 1; off < 32; off <<= 1) {
            int u = __shfl_up_sync(0xffffffffu, val, off);
            if (lane >= off) val += u;
        }
        if (lane == 31) wsums[wid] = val;
        __syncthreads();
        if (wid == 0) {
            int wv = wsums[lane];
            int wval = wv;
#pragma unroll
            for (int off = 1; off < 32; off <<= 1) {
                int u = __shfl_up_sync(0xffffffffu, wval, off);
                if (lane >= off) wval += u;
            }
            wsums[lane] = wval - wv;  // exclusive warp offsets
        }
        __syncthreads();
        int excl = s_carry + wsums[wid] + (val - v);
        if (i < n) { g_rowptr[i] = excl; g_cursor[i] = excl; }
        __syncthreads();
        if (t == 1023) s_carry = excl + v;  // running total
        __syncthreads();
    }
    if (t == 0) g_rowptr[n] = s_carry;
}

__global__ void scatter_kernel(const int* __restrict__ src,
                               const int* __restrict__ dst, int e) {
    int i = blockIdx.x * blockDim.x + threadIdx.x;
    if (i < e) {
        int d = dst[i];
        int pos = atomicAdd(&g_cursor[d], 1);
        g_esrc[pos] = src[i];
    }
}

// ---------------- mean aggregation: warp per destination node ----------------
template <int D>
__global__ void agg_kernel(const float* __restrict__ h, float* __restrict__ out, int n) {
    int gw = (blockIdx.x * blockDim.x + threadIdx.x) >> 5;
    if (gw >= n) return;
    int lane = threadIdx.x & 31;
    int beg = g_rowptr[gw], end = g_rowptr[gw + 1];
    constexpr int V = D / 128;  // float4 per lane
    float4 acc[V];
#pragma unroll
    for (int v = 0; v < V; v++) acc[v] = make_float4(0.f, 0.f, 0.f, 0.f);

    int e = beg;
    for (; e + 2 <= end; e += 2) {  // MLP=2
        int s0 = g_esrc[e], s1 = g_esrc[e + 1];
        const float4* r0 = reinterpret_cast<const float4*>(h + (size_t)s0 * D) + lane;
        const float4* r1 = reinterpret_cast<const float4*>(h + (size_t)s1 * D) + lane;
#pragma unroll
        for (int v = 0; v < V; v++) {
            float4 t0 = r0[32 * v], t1 = r1[32 * v];
            acc[v].x += t0.x + t1.x;
            acc[v].y += t0.y + t1.y;
            acc[v].z += t0.z + t1.z;
            acc[v].w += t0.w + t1.w;
        }
    }
    if (e < end) {
        int s0 = g_esrc[e];
        const float4* r0 = reinterpret_cast<const float4*>(h + (size_t)s0 * D) + lane;
#pragma unroll
        for (int v = 0; v < V; v++) {
            float4 t0 = r0[32 * v];
            acc[v].x += t0.x; acc[v].y += t0.y; acc[v].z += t0.z; acc[v].w += t0.w;
        }
    }
    int cnt = end - beg;
    float inv = 1.0f / (float)(cnt > 0 ? cnt : 1);
    float4* o = reinterpret_cast<float4*>(out + (size_t)gw * D) + lane;
#pragma unroll
    for (int v = 0; v < V; v++) {
        float4 a = acc[v];
        a.x *= inv; a.y *= inv; a.z *= inv; a.w *= inv;
        o[32 * v] = a;
    }
}

// ---------------- GEMM (M x K) @ (K x 128) + bias + relu -> out cols [off,off+128)
// BM=128, BN=128, BK=16; 256 threads; 8x8 per thread (split 4+4 in each dim)
__global__ void __launch_bounds__(256)
gemm_bias_relu(const float* __restrict__ A, const float* __restrict__ W,
               const float* __restrict__ bias, float* __restrict__ out,
               int M, int K, int colOffset) {
    __shared__ float As[16][128];
    __shared__ float Bs[16][128];
    const int t = threadIdx.x;
    const int row0 = blockIdx.x * 128;
    const int tr = t >> 4;          // 0..15
    const int tc = t & 15;          // 0..15

    const int ar = t >> 2;          // 0..63
    const int ak = (t & 3) << 2;    // 0,4,8,12
    const int bk = t >> 4;          // 0..15
    const int bc = (t & 15) << 3;   // 0..120

    float acc[8][8];
#pragma unroll
    for (int i = 0; i < 8; i++)
#pragma unroll
        for (int j = 0; j < 8; j++) acc[i][j] = 0.f;

    for (int k0 = 0; k0 < K; k0 += 16) {
#pragma unroll
        for (int i = 0; i < 2; i++) {
            int r = row0 + ar + i * 64;
            float4 v = make_float4(0.f, 0.f, 0.f, 0.f);
            if (r < M) v = *reinterpret_cast<const float4*>(A + (size_t)r * K + k0 + ak);
            As[ak + 0][ar + i * 64] = v.x;
            As[ak + 1][ar + i * 64] = v.y;
            As[ak + 2][ar + i * 64] = v.z;
            As[ak + 3][ar + i * 64] = v.w;
        }
#pragma unroll
        for (int i = 0; i < 2; i++) {
            float4 v = *reinterpret_cast<const float4*>(W + (size_t)(k0 + bk) * 128 + bc + i * 4);
            *reinterpret_cast<float4*>(&Bs[bk][bc + i * 4]) = v;
        }
        __syncthreads();
#pragma unroll
        for (int k = 0; k < 16; k++) {
            float4 a0 = *reinterpret_cast<const float4*>(&As[k][tr * 4]);
            float4 a1 = *reinterpret_cast<const float4*>(&As[k][tr * 4 + 64]);
            float4 b0 = *reinterpret_cast<const float4*>(&Bs[k][tc * 4]);
            float4 b1 = *reinterpret_cast<const float4*>(&Bs[k][tc * 4 + 64]);
            float a[8] = {a0.x, a0.y, a0.z, a0.w, a1.x, a1.y, a1.z, a1.w};
            float b[8] = {b0.x, b0.y, b0.z, b0.w, b1.x, b1.y, b1.z, b1.w};
#pragma unroll
            for (int i = 0; i < 8; i++)
#pragma unroll
                for (int j = 0; j < 8; j++)
                    acc[i][j] = fmaf(a[i], b[j], acc[i][j]);
        }
        __syncthreads();
    }

    float bloc[8];
#pragma unroll
    for (int j = 0; j < 4; j++) {
        bloc[j]     = bias[tc * 4 + j];
        bloc[j + 4] = bias[64 + tc * 4 + j];
    }
#pragma unroll
    for (int i = 0; i < 8; i++) {
        int r = row0 + ((i < 4) ? (tr * 4 + i) : (64 + tr * 4 + (i - 4)));
        if (r < M) {
            float4 v0, v1;
            v0.x = fmaxf(acc[i][0] + bloc[0], 0.f);
            v0.y = fmaxf(acc[i][1] + bloc[1], 0.f);
            v0.z = fmaxf(acc[i][2] + bloc[2], 0.f);
            v0.w = fmaxf(acc[i][3] + bloc[3], 0.f);
            v1.x = fmaxf(acc[i][4] + bloc[4], 0.f);
            v1.y = fmaxf(acc[i][5] + bloc[5], 0.f);
            v1.z = fmaxf(acc[i][6] + bloc[6], 0.f);
            v1.w = fmaxf(acc[i][7] + bloc[7], 0.f);
            *reinterpret_cast<float4*>(out + (size_t)r * HD + colOffset + tc * 4) = v0;
            *reinterpret_cast<float4*>(out + (size_t)r * HD + colOffset + 64 + tc * 4) = v1;
        }
    }
}

// ---------------- row-wise L2 normalize over HD=256 --------------------------
__global__ void norm_kernel(float* __restrict__ h, int n) {
    int gw = (blockIdx.x * blockDim.x + threadIdx.x) >> 5;
    if (gw >= n) return;
    int lane = threadIdx.x & 31;
    float4* row = reinterpret_cast<float4*>(h + (size_t)gw * HD) + lane;
    float4 v0 = row[0], v1 = row[32];
    float s = v0.x * v0.x + v0.y * v0.y + v0.z * v0.z + v0.w * v0.w +
              v1.x * v1.x + v1.y * v1.y + v1.z * v1.z + v1.w * v1.w;
#pragma unroll
    for (int off = 16; off; off >>= 1) s += __shfl_xor_sync(0xffffffffu, s, off);
    float scale = 1.0f / fmaxf(sqrtf(s), 1e-12f);
    v0.x *= scale; v0.y *= scale; v0.z *= scale; v0.w *= scale;
    v1.x *= scale; v1.y *= scale; v1.z *= scale; v1.w *= scale;
    row[0] = v0;
    row[32] = v1;
}

// ---------------- final FC: (M x 256) @ (256 x 40) + bias --------------------
__global__ void __launch_bounds__(128)
fc_kernel(const float* __restrict__ A, const float* __restrict__ W,
          const float* __restrict__ bias, float* __restrict__ out, int M) {
    __shared__ float As[16][64];
    __shared__ float Ws[16][40];
    int t = threadIdx.x;
    int row0 = blockIdx.x * 64;
    int tr = t >> 3;  // 0..15 -> rows tr*4..tr*4+3
    int tc = t & 7;   // 0..7  -> cols tc*5..tc*5+4
    int ar = t >> 1;          // 0..63
    int ak = (t & 1) * 8;     // 0 or 8

    float acc[4][5];
#pragma unroll
    for (int i = 0; i < 4; i++)
#pragma unroll
        for (int j = 0; j < 5; j++) acc[i][j] = 0.f;

    for (int k0 = 0; k0 < HD; k0 += 16) {
        {
            int r = row0 + ar;
            float4 u0 = make_float4(0.f, 0.f, 0.f, 0.f), u1 = u0;
            if (r < M) {
                u0 = *reinterpret_cast<const float4*>(A + (size_t)r * HD + k0 + ak);
                u1 = *reinterpret_cast<const float4*>(A + (size_t)r * HD + k0 + ak + 4);
            }
            As[ak + 0][ar] = u0.x; As[ak + 1][ar] = u0.y;
            As[ak + 2][ar] = u0.z; As[ak + 3][ar] = u0.w;
            As[ak + 4][ar] = u1.x; As[ak + 5][ar] = u1.y;
            As[ak + 6][ar] = u1.z; As[ak + 7][ar] = u1.w;
        }
#pragma unroll
        for (int i = 0; i < 5; i++) {
            int idx = t + 128 * i;  // 0..639 = 16*40
            int kk = idx / 40, cc = idx - kk * 40;
            Ws[kk][cc] = W[(size_t)(k0 + kk) * NCLS + cc];
        }
        __syncthreads();
#pragma unroll
        for (int k = 0; k < 16; k++) {
            float4 av = *reinterpret_cast<const float4*>(&As[k][tr * 4]);
            float a[4] = {av.x, av.y, av.z, av.w};
            float w[5];
#pragma unroll
            for (int j = 0; j < 5; j++) w[j] = Ws[k][tc * 5 + j];
#pragma unroll
            for (int i = 0; i < 4; i++)
#pragma unroll
                for (int j = 0; j < 5; j++)
                    acc[i][j] = fmaf(a[i], w[j], acc[i][j]);
        }
        __syncthreads();
    }
#pragma unroll
    for (int i = 0; i < 4; i++) {
        int r = row0 + tr * 4 + i;
        if (r < M) {
#pragma unroll
            for (int j = 0; j < 5; j++)
                out[(size_t)r * NCLS + tc * 5 + j] = acc[i][j] + bias[tc * 5 + j];
        }
    }
}

// ---------------- launch ------------------------------------------------------
extern "C" void kernel_launch(void* const* d_in, const int* in_sizes, int n_in,
                              void* d_out, int out_size) {
    const float* x   = (const float*)d_in[0];
    const int*   src = (const int*)d_in[1];
    const int*   dst = (const int*)d_in[2];
    const float* w1s = (const float*)d_in[3];
    const float* b1s = (const float*)d_in[4];
    const float* w1n = (const float*)d_in[5];
    const float* b1n = (const float*)d_in[6];
    const float* w2s = (const float*)d_in[7];
    const float* b2s = (const float*)d_in[8];
    const float* w2n = (const float*)d_in[9];
    const float* b2n = (const float*)d_in[10];
    const float* wfc = (const float*)d_in[11];
    const float* bfc = (const float*)d_in[12];

    int N_ = in_sizes[0] / 128;
    int E_ = in_sizes[1];

    float *neigh, *h1, *h2;
    cudaGetSymbolAddress((void**)&neigh, g_neigh);
    cudaGetSymbolAddress((void**)&h1, g_h1);
    cudaGetSymbolAddress((void**)&h2, g_h2);

    int eblocks = (E_ + 255) / 256;
    int nblocks = (N_ + 255) / 256;
    int wblocks = (N_ * 32 + 255) / 256;   // warp-per-node kernels
    int gblocks = (N_ + 127) / 128;        // gemm row tiles

    // CSR build (per call; graph is an input)
    zero_deg_kernel<<<nblocks, 256>>>(N_);
    count_kernel<<<eblocks, 256>>>(dst, E_);
    scan_kernel<<<1, 1024>>>(N_);
    scatter_kernel<<<eblocks, 256>>>(src, dst, E_);

    // layer 1
    agg_kernel<128><<<wblocks, 256>>>(x, neigh, N_);
    gemm_bias_relu<<<gblocks, 256>>>(x,     w1s, b1s, h1, N_, 128, 0);
    gemm_bias_relu<<<gblocks, 256>>>(neigh, w1n, b1n, h1, N_, 128, 128);
    norm_kernel<<<wblocks, 256>>>(h1, N_);

    // layer 2
    agg_kernel<256><<<wblocks, 256>>>(h1, neigh, N_);
    gemm_bias_relu<<<gblocks, 256>>>(h1,    w2s, b2s, h2, N_, 256, 0);
    gemm_bias_relu<<<gblocks, 256>>>(neigh, w2n, b2n, h2, N_, 256, 128);
    norm_kernel<<<wblocks, 256>>>(h2, N_);

    // head
    fc_kernel<<<(N_ + 63) / 64, 128>>>(h2, wfc, bfc, (float*)d_out, N_);
}

// round 2
// speedup vs baseline: 1.5396x; 1.5396x over previous
#include <cuda_runtime.h>
#include <cstdint>

#define NMAX 100000
#define EMAX 1600000
#define HD   256      // concat hidden dim (2*128)
#define NCLS 40

// ---------------- scratch (static device globals; no allocation) -------------
__device__ int   g_deg[NMAX];
__device__ int   g_rowptr[NMAX + 1];
__device__ int   g_cursor[NMAX];
__device__ int   g_esrc[EMAX];
__device__ float g_t[(size_t)NMAX * 128];    // neighbor-branch pre-aggregation
__device__ float g_h1[(size_t)NMAX * HD];
__device__ float g_h2[(size_t)NMAX * HD];
__device__ float g_inv1[NMAX];
__device__ float g_inv2[NMAX];

// ---------------- tf32 helpers ------------------------------------------------
__device__ __forceinline__ uint32_t f2tf32(float f) {
    uint32_t r;
    asm("cvt.rna.tf32.f32 %0, %1;" : "=r"(r) : "f"(f));
    return r;
}

__device__ __forceinline__ void mma_tf32(float& c0, float& c1, float& c2, float& c3,
                                         uint32_t a0, uint32_t a1, uint32_t a2, uint32_t a3,
                                         uint32_t b0, uint32_t b1) {
    asm volatile(
        "mma.sync.aligned.m16n8k8.row.col.f32.tf32.tf32.f32 "
        "{%0,%1,%2,%3}, {%4,%5,%6,%7}, {%8,%9}, {%0,%1,%2,%3};"
        : "+f"(c0), "+f"(c1), "+f"(c2), "+f"(c3)
        : "r"(a0), "r"(a1), "r"(a2), "r"(a3), "r"(b0), "r"(b1));
}

// ---------------- CSR build --------------------------------------------------
__global__ void zero_deg_kernel(int n) {
    int i = blockIdx.x * blockDim.x + threadIdx.x;
    if (i < n) g_deg[i] = 0;
}

__global__ void count_kernel(const int* __restrict__ dst, int e) {
    int i = blockIdx.x * blockDim.x + threadIdx.x;
    if (i < e) atomicAdd(&g_deg[dst[i]], 1);
}

// single-block exclusive scan of g_deg -> g_rowptr (+ copy into g_cursor)
__global__ void scan_kernel(int n) {
    __shared__ int wsums[32];
    __shared__ int s_carry;
    int t = threadIdx.x, lane = t & 31, wid = t >> 5;
    if (t == 0) s_carry = 0;
    __syncthreads();
    for (int base = 0; base < n; base += 1024) {
        int i = base + t;
        int v = (i < n) ? g_deg[i] : 0;
        int val = v;
#pragma unroll
        for (int off = 1; off < 32; off <<= 1) {
            int u = __shfl_up_sync(0xffffffffu, val, off);
            if (lane >= off) val += u;
        }
        if (lane == 31) wsums[wid] = val;
        __syncthreads();
        if (wid == 0) {
            int wv = wsums[lane];
            int wval = wv;
#pragma unroll
            for (int off = 1; off < 32; off <<= 1) {
                int u = __shfl_up_sync(0xffffffffu, wval, off);
                if (lane >= off) wval += u;
            }
            wsums[lane] = wval - wv;  // exclusive warp offsets
        }
        __syncthreads();
        int excl = s_carry + wsums[wid] + (val - v);
        if (i < n) { g_rowptr[i] = excl; g_cursor[i] = excl; }
        __syncthreads();
        if (t == 1023) s_carry = excl + v;  // running total
        __syncthreads();
    }
    if (t == 0) g_rowptr[n] = s_carry;
}

__global__ void scatter_kernel(const int* __restrict__ src,
                               const int* __restrict__ dst, int e) {
    int i = blockIdx.x * blockDim.x + threadIdx.x;
    if (i < e) {
        int d = dst[i];
        int pos = atomicAdd(&g_cursor[d], 1);
        g_esrc[pos] = src[i];
    }
}

// ---------------- mean aggregation over 128-wide rows + bias + relu ----------
// out[node*ldo + c] = relu(mean_{e in N(node)} t[src_e][c] + bias[c])
__global__ void agg_bias_relu(const float* __restrict__ t, const float* __restrict__ bias,
                              float* __restrict__ out, int ldo, int n) {
    int gw = (blockIdx.x * blockDim.x + threadIdx.x) >> 5;
    if (gw >= n) return;
    int lane = threadIdx.x & 31;
    int beg = g_rowptr[gw], end = g_rowptr[gw + 1];
    float4 acc = make_float4(0.f, 0.f, 0.f, 0.f);
    int e = beg;
    for (; e + 4 <= end; e += 4) {
        int s0 = g_esrc[e], s1 = g_esrc[e + 1], s2 = g_esrc[e + 2], s3 = g_esrc[e + 3];
        float4 t0 = *(reinterpret_cast<const float4*>(t + (size_t)s0 * 128) + lane);
        float4 t1 = *(reinterpret_cast<const float4*>(t + (size_t)s1 * 128) + lane);
        float4 t2 = *(reinterpret_cast<const float4*>(t + (size_t)s2 * 128) + lane);
        float4 t3 = *(reinterpret_cast<const float4*>(t + (size_t)s3 * 128) + lane);
        acc.x += (t0.x + t1.x) + (t2.x + t3.x);
        acc.y += (t0.y + t1.y) + (t2.y + t3.y);
        acc.z += (t0.z + t1.z) + (t2.z + t3.z);
        acc.w += (t0.w + t1.w) + (t2.w + t3.w);
    }
    for (; e < end; ++e) {
        int s0 = g_esrc[e];
        float4 t0 = *(reinterpret_cast<const float4*>(t + (size_t)s0 * 128) + lane);
        acc.x += t0.x; acc.y += t0.y; acc.z += t0.z; acc.w += t0.w;
    }
    int cnt = end - beg;
    float inv = 1.0f / (float)(cnt > 0 ? cnt : 1);
    float4 b = *(reinterpret_cast<const float4*>(bias) + lane);
    float4 o;
    o.x = fmaxf(acc.x * inv + b.x, 0.f);
    o.y = fmaxf(acc.y * inv + b.y, 0.f);
    o.z = fmaxf(acc.z * inv + b.z, 0.f);
    o.w = fmaxf(acc.w * inv + b.w, 0.f);
    *(reinterpret_cast<float4*>(out + (size_t)gw * ldo) + lane) = o;
}

// ---------------- per-row 1/max(||row||,eps) over HD=256 ---------------------
__global__ void invnorm_kernel(const float* __restrict__ h, float* __restrict__ invn, int n) {
    int gw = (blockIdx.x * blockDim.x + threadIdx.x) >> 5;
    if (gw >= n) return;
    int lane = threadIdx.x & 31;
    const float4* row = reinterpret_cast<const float4*>(h + (size_t)gw * HD) + lane;
    float4 v0 = row[0], v1 = row[32];
    float s = v0.x * v0.x + v0.y * v0.y + v0.z * v0.z + v0.w * v0.w +
              v1.x * v1.x + v1.y * v1.y + v1.z * v1.z + v1.w * v1.w;
#pragma unroll
    for (int off = 16; off; off >>= 1) s += __shfl_xor_sync(0xffffffffu, s, off);
    if (lane == 0) invn[gw] = 1.0f / fmaxf(sqrtf(s), 1e-12f);
}

// ---------------- tf32 tensor-core GEMM: out[M x 128] = (A .* rowScale) @ W ---
// A: [M x lda] fp32 (uses first K cols); W: [K x 128] row-major.
// BM=128, BN=128, BK=16; 256 threads, 8 warps (2m x 4n), warp tile 64x32.
#define SMS 136

__global__ void __launch_bounds__(256)
gemm_tc(const float* __restrict__ A, int lda, const float* __restrict__ rowScale,
        const float* __restrict__ W, const float* __restrict__ bias,
        float* __restrict__ out, int ldo, int M, int K, int doRelu) {
    __shared__ uint32_t As[2][16][SMS];  // [k][m], transposed
    __shared__ uint32_t Bs[2][16][SMS];  // [k][n]

    const int t = threadIdx.x;
    const int warp = t >> 5, lane = t & 31;
    const int wm = warp & 1, wn = warp >> 1;   // 2 x 4 warp grid
    const int grp = lane >> 2, qid = lane & 3;
    const int row0 = blockIdx.x * 128;

    // A loader: row = t&127, column groups cg = (t>>7) + 2*i (4 floats each)
    const int ar = t & 127;
    const int acg0 = t >> 7;
    const int gr = row0 + ar;
    const bool arOK = (gr < M);
    float ascale = 1.0f;
    if (rowScale != nullptr && arOK) ascale = rowScale[gr];

    float acc[4][4][4];
#pragma unroll
    for (int i = 0; i < 4; i++)
#pragma unroll
        for (int j = 0; j < 4; j++)
#pragma unroll
            for (int c = 0; c < 4; c++) acc[i][j][c] = 0.f;

    float4 apre[2], bpre[2];

    auto loadAB = [&](int k0) {
#pragma unroll
        for (int i = 0; i < 2; i++) {
            int cg = acg0 + 2 * i;
            apre[i] = arOK ? *reinterpret_cast<const float4*>(A + (size_t)gr * lda + k0 + cg * 4)
                           : make_float4(0.f, 0.f, 0.f, 0.f);
        }
#pragma unroll
        for (int i = 0; i < 2; i++) {
            int idx = t + 256 * i;
            int kk = idx >> 5, nq = (idx & 31) * 4;
            bpre[i] = *reinterpret_cast<const float4*>(W + (size_t)(k0 + kk) * 128 + nq);
        }
    };
    auto storeAB = [&](int st) {
#pragma unroll
        for (int i = 0; i < 2; i++) {
            int cg = acg0 + 2 * i;
            float4 v = apre[i];
            As[st][cg * 4 + 0][ar] = f2tf32(v.x * ascale);
            As[st][cg * 4 + 1][ar] = f2tf32(v.y * ascale);
            As[st][cg * 4 + 2][ar] = f2tf32(v.z * ascale);
            As[st][cg * 4 + 3][ar] = f2tf32(v.w * ascale);
        }
#pragma unroll
        for (int i = 0; i < 2; i++) {
            int idx = t + 256 * i;
            int kk = idx >> 5, nq = (idx & 31) * 4;
            uint4 u;
            u.x = f2tf32(bpre[i].x); u.y = f2tf32(bpre[i].y);
            u.z = f2tf32(bpre[i].z); u.w = f2tf32(bpre[i].w);
            *reinterpret_cast<uint4*>(&Bs[st][kk][nq]) = u;
        }
    };

    loadAB(0);
    storeAB(0);
    __syncthreads();

    const int nT = K / 16;
    int cur = 0;
    for (int tile = 0; tile < nT; ++tile) {
        bool has = (tile + 1 < nT);
        if (has) loadAB((tile + 1) * 16);
#pragma unroll
        for (int s = 0; s < 2; ++s) {
            const int k8 = s * 8;
            uint32_t af[4][4], bf[4][2];
#pragma unroll
            for (int mt = 0; mt < 4; ++mt) {
                int m = wm * 64 + mt * 16 + grp;
                af[mt][0] = As[cur][k8 + qid][m];
                af[mt][1] = As[cur][k8 + qid][m + 8];
                af[mt][2] = As[cur][k8 + qid + 4][m];
                af[mt][3] = As[cur][k8 + qid + 4][m + 8];
            }
#pragma unroll
            for (int nt = 0; nt < 4; ++nt) {
                int n = wn * 32 + nt * 8 + grp;
                bf[nt][0] = Bs[cur][k8 + qid][n];
                bf[nt][1] = Bs[cur][k8 + qid + 4][n];
            }
#pragma unroll
            for (int mt = 0; mt < 4; ++mt)
#pragma unroll
                for (int nt = 0; nt < 4; ++nt)
                    mma_tf32(acc[mt][nt][0], acc[mt][nt][1], acc[mt][nt][2], acc[mt][nt][3],
                             af[mt][0], af[mt][1], af[mt][2], af[mt][3],
                             bf[nt][0], bf[nt][1]);
        }
        if (has) storeAB(cur ^ 1);
        __syncthreads();
        cur ^= 1;
    }

    // epilogue
#pragma unroll
    for (int mt = 0; mt < 4; ++mt) {
        int rbase = row0 + wm * 64 + mt * 16 + grp;
#pragma unroll
        for (int nt = 0; nt < 4; ++nt) {
            int col = wn * 32 + nt * 8 + qid * 2;
            float b0 = 0.f, b1 = 0.f;
            if (bias != nullptr) { b0 = bias[col]; b1 = bias[col + 1]; }
            if (rbase < M) {
                float2 v;
                v.x = acc[mt][nt][0] + b0;
                v.y = acc[mt][nt][1] + b1;
                if (doRelu) { v.x = fmaxf(v.x, 0.f); v.y = fmaxf(v.y, 0.f); }
                *reinterpret_cast<float2*>(out + (size_t)rbase * ldo + col) = v;
            }
            if (rbase + 8 < M) {
                float2 v;
                v.x = acc[mt][nt][2] + b0;
                v.y = acc[mt][nt][3] + b1;
                if (doRelu) { v.x = fmaxf(v.x, 0.f); v.y = fmaxf(v.y, 0.f); }
                *reinterpret_cast<float2*>(out + (size_t)(rbase + 8) * ldo + col) = v;
            }
        }
    }
}

// ---------------- final FC: ((A .* inv) [M x 256]) @ W[256 x 40] + bias ------
__global__ void __launch_bounds__(128)
fc_kernel(const float* __restrict__ A, const float* __restrict__ inv,
          const float* __restrict__ W, const float* __restrict__ bias,
          float* __restrict__ out, int M) {
    __shared__ float As[16][64];
    __shared__ float Ws[16][40];
    int t = threadIdx.x;
    int row0 = blockIdx.x * 64;
    int tr = t >> 3;  // 0..15 -> rows tr*4..tr*4+3
    int tc = t & 7;   // 0..7  -> cols tc*5..tc*5+4
    int ar = t >> 1;          // 0..63
    int ak = (t & 1) * 8;     // 0 or 8

    int rA = row0 + ar;
    float sc = (rA < M) ? inv[rA] : 0.f;

    float acc[4][5];
#pragma unroll
    for (int i = 0; i < 4; i++)
#pragma unroll
        for (int j = 0; j < 5; j++) acc[i][j] = 0.f;

    for (int k0 = 0; k0 < HD; k0 += 16) {
        {
            float4 u0 = make_float4(0.f, 0.f, 0.f, 0.f), u1 = u0;
            if (rA < M) {
                u0 = *reinterpret_cast<const float4*>(A + (size_t)rA * HD + k0 + ak);
                u1 = *reinterpret_cast<const float4*>(A + (size_t)rA * HD + k0 + ak + 4);
            }
            As[ak + 0][ar] = u0.x * sc; As[ak + 1][ar] = u0.y * sc;
            As[ak + 2][ar] = u0.z * sc; As[ak + 3][ar] = u0.w * sc;
            As[ak + 4][ar] = u1.x * sc; As[ak + 5][ar] = u1.y * sc;
            As[ak + 6][ar] = u1.z * sc; As[ak + 7][ar] = u1.w * sc;
        }
#pragma unroll
        for (int i = 0; i < 5; i++) {
            int idx = t + 128 * i;  // 0..639 = 16*40
            int kk = idx / 40, cc = idx - kk * 40;
            Ws[kk][cc] = W[(size_t)(k0 + kk) * NCLS + cc];
        }
        __syncthreads();
#pragma unroll
        for (int k = 0; k < 16; k++) {
            float4 av = *reinterpret_cast<const float4*>(&As[k][tr * 4]);
            float a[4] = {av.x, av.y, av.z, av.w};
            float w[5];
#pragma unroll
            for (int j = 0; j < 5; j++) w[j] = Ws[k][tc * 5 + j];
#pragma unroll
            for (int i = 0; i < 4; i++)
#pragma unroll
                for (int j = 0; j < 5; j++)
                    acc[i][j] = fmaf(a[i], w[j], acc[i][j]);
        }
        __syncthreads();
    }
#pragma unroll
    for (int i = 0; i < 4; i++) {
        int r = row0 + tr * 4 + i;
        if (r < M) {
#pragma unroll
            for (int j = 0; j < 5; j++)
                out[(size_t)r * NCLS + tc * 5 + j] = acc[i][j] + bias[tc * 5 + j];
        }
    }
}

// ---------------- launch ------------------------------------------------------
extern "C" void kernel_launch(void* const* d_in, const int* in_sizes, int n_in,
                              void* d_out, int out_size) {
    const float* x   = (const float*)d_in[0];
    const int*   src = (const int*)d_in[1];
    const int*   dst = (const int*)d_in[2];
    const float* w1s = (const float*)d_in[3];
    const float* b1s = (const float*)d_in[4];
    const float* w1n = (const float*)d_in[5];
    const float* b1n = (const float*)d_in[6];
    const float* w2s = (const float*)d_in[7];
    const float* b2s = (const float*)d_in[8];
    const float* w2n = (const float*)d_in[9];
    const float* b2n = (const float*)d_in[10];
    const float* wfc = (const float*)d_in[11];
    const float* bfc = (const float*)d_in[12];

    int N_ = in_sizes[0] / 128;
    int E_ = in_sizes[1];

    float *tbuf, *h1, *h2, *inv1, *inv2;
    cudaGetSymbolAddress((void**)&tbuf, g_t);
    cudaGetSymbolAddress((void**)&h1, g_h1);
    cudaGetSymbolAddress((void**)&h2, g_h2);
    cudaGetSymbolAddress((void**)&inv1, g_inv1);
    cudaGetSymbolAddress((void**)&inv2, g_inv2);

    int eblocks = (E_ + 255) / 256;
    int nblocks = (N_ + 255) / 256;
    int wblocks = (N_ * 32 + 255) / 256;   // warp-per-node kernels
    int gblocks = (N_ + 127) / 128;        // gemm row tiles

    // CSR build (per call; graph is an input)
    zero_deg_kernel<<<nblocks, 256>>>(N_);
    count_kernel<<<eblocks, 256>>>(dst, E_);
    scan_kernel<<<1, 1024>>>(N_);
    scatter_kernel<<<eblocks, 256>>>(src, dst, E_);

    // ---- layer 1 ----
    // self branch: h1[:, 0:128] = relu(x @ w1s + b1s)
    gemm_tc<<<gblocks, 256>>>(x, 128, nullptr, w1s, b1s, h1, HD, N_, 128, 1);
    // neighbor pre-branch: t = x @ w1n (agg moved after GEMM: Mean(x)@W == Mean(x@W))
    gemm_tc<<<gblocks, 256>>>(x, 128, nullptr, w1n, nullptr, tbuf, 128, N_, 128, 0);
    // h1[:, 128:256] = relu(Mean(t) + b1n)
    agg_bias_relu<<<wblocks, 256>>>(tbuf, b1n, h1 + 128, HD, N_);
    // row inverse norms of h1 (folded into layer-2 A loads)
    invnorm_kernel<<<wblocks, 256>>>(h1, inv1, N_);

    // ---- layer 2 ----
    gemm_tc<<<gblocks, 256>>>(h1, HD, inv1, w2s, b2s, h2, HD, N_, HD, 1);
    gemm_tc<<<gblocks, 256>>>(h1, HD, inv1, w2n, nullptr, tbuf, 128, N_, HD, 0);
    agg_bias_relu<<<wblocks, 256>>>(tbuf, b2n, h2 + 128, HD, N_);
    invnorm_kernel<<<wblocks, 256>>>(h2, inv2, N_);

    // ---- head ----
    fc_kernel<<<(N_ + 63) / 64, 128>>>(h2, inv2, wfc, bfc, (float*)d_out, N_);
}

// round 3
// speedup vs baseline: 1.6146x; 1.0487x over previous
#include <cuda_runtime.h>
#include <cstdint>

#define NMAX 100000
#define EMAX 1600000
#define HD   256      // concat hidden dim (2*128)
#define NCLS 40

// ---------------- scratch (static device globals; no allocation) -------------
__device__ int   g_deg[NMAX];
__device__ int   g_rowptr[NMAX + 1];
__device__ int   g_cursor[NMAX];
__device__ int   g_esrc[EMAX];
__device__ float g_t[(size_t)NMAX * 128];    // neighbor-branch pre-aggregation
__device__ float g_h1[(size_t)NMAX * HD];
__device__ float g_h2[(size_t)NMAX * HD];
__device__ float g_inv1[NMAX];
__device__ float g_inv2[NMAX];

// ---------------- tf32 helpers ------------------------------------------------
__device__ __forceinline__ uint32_t f2tf32(float f) {
    uint32_t r;
    asm("cvt.rna.tf32.f32 %0, %1;" : "=r"(r) : "f"(f));
    return r;
}

__device__ __forceinline__ void mma_tf32(float& c0, float& c1, float& c2, float& c3,
                                         uint32_t a0, uint32_t a1, uint32_t a2, uint32_t a3,
                                         uint32_t b0, uint32_t b1) {
    asm volatile(
        "mma.sync.aligned.m16n8k8.row.col.f32.tf32.tf32.f32 "
        "{%0,%1,%2,%3}, {%4,%5,%6,%7}, {%8,%9}, {%0,%1,%2,%3};"
        : "+f"(c0), "+f"(c1), "+f"(c2), "+f"(c3)
        : "r"(a0), "r"(a1), "r"(a2), "r"(a3), "r"(b0), "r"(b1));
}

// ---------------- CSR build --------------------------------------------------
__global__ void count_kernel(const int* __restrict__ dst, int e) {
    int i = blockIdx.x * blockDim.x + threadIdx.x;
    if (i < e) atomicAdd(&g_deg[dst[i]], 1);
}

// single-block exclusive scan of g_deg -> g_rowptr (+ copy into g_cursor)
__global__ void scan_kernel(int n) {
    __shared__ int wsums[32];
    __shared__ int s_carry;
    int t = threadIdx.x, lane = t & 31, wid = t >> 5;
    if (t == 0) s_carry = 0;
    __syncthreads();
    for (int base = 0; base < n; base += 1024) {
        int i = base + t;
        int v = (i < n) ? g_deg[i] : 0;
        int val = v;
#pragma unroll
        for (int off = 1; off < 32; off <<= 1) {
            int u = __shfl_up_sync(0xffffffffu, val, off);
            if (lane >= off) val += u;
        }
        if (lane == 31) wsums[wid] = val;
        __syncthreads();
        if (wid == 0) {
            int wv = wsums[lane];
            int wval = wv;
#pragma unroll
            for (int off = 1; off < 32; off <<= 1) {
                int u = __shfl_up_sync(0xffffffffu, wval, off);
                if (lane >= off) wval += u;
            }
            wsums[lane] = wval - wv;  // exclusive warp offsets
        }
        __syncthreads();
        int excl = s_carry + wsums[wid] + (val - v);
        if (i < n) { g_rowptr[i] = excl; g_cursor[i] = excl; }
        __syncthreads();
        if (t == 1023) s_carry = excl + v;  // running total
        __syncthreads();
    }
    if (t == 0) g_rowptr[n] = s_carry;
}

__global__ void scatter_kernel(const int* __restrict__ src,
                               const int* __restrict__ dst, int e) {
    int i = blockIdx.x * blockDim.x + threadIdx.x;
    if (i < e) {
        int d = dst[i];
        int pos = atomicAdd(&g_cursor[d], 1);
        g_esrc[pos] = src[i];
    }
}

// ------ mean aggregation (128-wide) + bias + relu + fused row L2-invnorm -----
// h row layout: [self(128) | neigh(128)], stride HD. Writes neigh half, then
// reads self half and emits invn[node] = 1/max(||row||,eps).
__global__ void agg_bias_relu_norm(const float* __restrict__ t, const float* __restrict__ bias,
                                   float* __restrict__ h, float* __restrict__ invn, int n) {
    int gw = (blockIdx.x * blockDim.x + threadIdx.x) >> 5;
    if (gw >= n) return;
    int lane = threadIdx.x & 31;
    int beg = g_rowptr[gw], end = g_rowptr[gw + 1];
    float4 acc = make_float4(0.f, 0.f, 0.f, 0.f);
    int e = beg;
    for (; e + 4 <= end; e += 4) {
        int s0 = g_esrc[e], s1 = g_esrc[e + 1], s2 = g_esrc[e + 2], s3 = g_esrc[e + 3];
        float4 t0 = *(reinterpret_cast<const float4*>(t + (size_t)s0 * 128) + lane);
        float4 t1 = *(reinterpret_cast<const float4*>(t + (size_t)s1 * 128) + lane);
        float4 t2 = *(reinterpret_cast<const float4*>(t + (size_t)s2 * 128) + lane);
        float4 t3 = *(reinterpret_cast<const float4*>(t + (size_t)s3 * 128) + lane);
        acc.x += (t0.x + t1.x) + (t2.x + t3.x);
        acc.y += (t0.y + t1.y) + (t2.y + t3.y);
        acc.z += (t0.z + t1.z) + (t2.z + t3.z);
        acc.w += (t0.w + t1.w) + (t2.w + t3.w);
    }
    for (; e < end; ++e) {
        int s0 = g_esrc[e];
        float4 t0 = *(reinterpret_cast<const float4*>(t + (size_t)s0 * 128) + lane);
        acc.x += t0.x; acc.y += t0.y; acc.z += t0.z; acc.w += t0.w;
    }
    int cnt = end - beg;
    float inv = 1.0f / (float)(cnt > 0 ? cnt : 1);
    float4 b = *(reinterpret_cast<const float4*>(bias) + lane);
    float4 o;
    o.x = fmaxf(acc.x * inv + b.x, 0.f);
    o.y = fmaxf(acc.y * inv + b.y, 0.f);
    o.z = fmaxf(acc.z * inv + b.z, 0.f);
    o.w = fmaxf(acc.w * inv + b.w, 0.f);
    float4* row = reinterpret_cast<float4*>(h + (size_t)gw * HD);
    row[32 + lane] = o;                       // neigh half
    float4 s4 = row[lane];                    // self half (written by GEMM)
    float s = s4.x * s4.x + s4.y * s4.y + s4.z * s4.z + s4.w * s4.w +
              o.x * o.x + o.y * o.y + o.z * o.z + o.w * o.w;
#pragma unroll
    for (int off = 16; off; off >>= 1) s += __shfl_xor_sync(0xffffffffu, s, off);
    if (lane == 0) invn[gw] = 1.0f / fmaxf(sqrtf(s), 1e-12f);
}

// ---- fused dual-output tf32 GEMM:
//   out1[M x 128] = relu((A .* rowScale) @ W1 + bias1)   (self branch)
//   out2[M x 128] =      (A .* rowScale) @ W2            (neighbor pre-branch)
// One shared A tile serves both halves. BM=128, BN=256, BK=16, 512 threads,
// warp grid 4m x 4n, warp tile 32x64.
#define SMSA 132
#define SMSB 260

__global__ void __launch_bounds__(512)
gemm_dual(const float* __restrict__ A, int lda, const float* __restrict__ rowScale,
          const float* __restrict__ W1, const float* __restrict__ W2,
          const float* __restrict__ bias1,
          float* __restrict__ out1, int ldo1, float* __restrict__ out2, int ldo2,
          int M, int K) {
    __shared__ uint32_t As[2][16][SMSA];  // [k][m] transposed
    __shared__ uint32_t Bs[2][16][SMSB];  // [k][n], n<128 from W1, n>=128 from W2

    const int t = threadIdx.x;
    const int warp = t >> 5, lane = t & 31;
    const int wm = warp & 3, wn = warp >> 2;   // 4 x 4 warp grid
    const int grp = lane >> 2, qid = lane & 3;
    const int row0 = blockIdx.x * 128;

    // A loader: one float4/thread: row ar, k-offset ak
    const int ar = t >> 2;          // 0..127
    const int ak = (t & 3) << 2;    // 0,4,8,12
    const int gr = row0 + ar;
    const bool arOK = (gr < M);
    float ascale = 1.0f;
    if (rowScale != nullptr && arOK) ascale = rowScale[gr];

    float acc[2][8][4];
#pragma unroll
    for (int i = 0; i < 2; i++)
#pragma unroll
        for (int j = 0; j < 8; j++)
#pragma unroll
            for (int c = 0; c < 4; c++) acc[i][j][c] = 0.f;

    float4 apre, bpre[2];

    auto loadAB = [&](int k0) {
        apre = arOK ? *reinterpret_cast<const float4*>(A + (size_t)gr * lda + k0 + ak)
                    : make_float4(0.f, 0.f, 0.f, 0.f);
#pragma unroll
        for (int i = 0; i < 2; i++) {
            int idx = t + 512 * i;          // float4 index, 1024 total
            int kk = idx >> 6;              // 0..15
            int nn = (idx & 63) << 2;       // 0..252
            const float* srcp = (nn < 128)
                ? (W1 + (size_t)(k0 + kk) * 128 + nn)
                : (W2 + (size_t)(k0 + kk) * 128 + (nn - 128));
            bpre[i] = *reinterpret_cast<const float4*>(srcp);
        }
    };
    auto storeAB = [&](int st) {
        As[st][ak + 0][ar] = f2tf32(apre.x * ascale);
        As[st][ak + 1][ar] = f2tf32(apre.y * ascale);
        As[st][ak + 2][ar] = f2tf32(apre.z * ascale);
        As[st][ak + 3][ar] = f2tf32(apre.w * ascale);
#pragma unroll
        for (int i = 0; i < 2; i++) {
            int idx = t + 512 * i;
            int kk = idx >> 6;
            int nn = (idx & 63) << 2;
            uint4 u;
            u.x = f2tf32(bpre[i].x); u.y = f2tf32(bpre[i].y);
            u.z = f2tf32(bpre[i].z); u.w = f2tf32(bpre[i].w);
            *reinterpret_cast<uint4*>(&Bs[st][kk][nn]) = u;
        }
    };

    loadAB(0);
    storeAB(0);
    __syncthreads();

    const int nT = K / 16;
    int cur = 0;
    for (int tile = 0; tile < nT; ++tile) {
        bool has = (tile + 1 < nT);
        if (has) loadAB((tile + 1) * 16);
#pragma unroll
        for (int s = 0; s < 2; ++s) {
            const int k8 = s * 8;
            uint32_t af[2][4], bf[8][2];
#pragma unroll
            for (int mt = 0; mt < 2; ++mt) {
                int m = wm * 32 + mt * 16 + grp;
                af[mt][0] = As[cur][k8 + qid][m];
                af[mt][1] = As[cur][k8 + qid][m + 8];
                af[mt][2] = As[cur][k8 + qid + 4][m];
                af[mt][3] = As[cur][k8 + qid + 4][m + 8];
            }
#pragma unroll
            for (int nt = 0; nt < 8; ++nt) {
                int n = wn * 64 + nt * 8 + grp;
                bf[nt][0] = Bs[cur][k8 + qid][n];
                bf[nt][1] = Bs[cur][k8 + qid + 4][n];
            }
#pragma unroll
            for (int mt = 0; mt < 2; ++mt)
#pragma unroll
                for (int nt = 0; nt < 8; ++nt)
                    mma_tf32(acc[mt][nt][0], acc[mt][nt][1], acc[mt][nt][2], acc[mt][nt][3],
                             af[mt][0], af[mt][1], af[mt][2], af[mt][3],
                             bf[nt][0], bf[nt][1]);
        }
        if (has) storeAB(cur ^ 1);
        __syncthreads();
        cur ^= 1;
    }

    // epilogue: cols [0,128) -> out1 (+bias1, relu); cols [128,256) -> out2 raw
#pragma unroll
    for (int mt = 0; mt < 2; ++mt) {
        int rbase = row0 + wm * 32 + mt * 16 + grp;
#pragma unroll
        for (int nt = 0; nt < 8; ++nt) {
            int col = wn * 64 + nt * 8 + qid * 2;
            bool isSelf = (col < 128);
            float b0 = 0.f, b1 = 0.f;
            if (isSelf) { b0 = bias1[col]; b1 = bias1[col + 1]; }
            float* outp;
            int c;
            if (isSelf) { outp = out1; c = col; }
            else        { outp = out2; c = col - 128; }
            int ldo = isSelf ? ldo1 : ldo2;
            if (rbase < M) {
                float2 v;
                v.x = acc[mt][nt][0] + b0;
                v.y = acc[mt][nt][1] + b1;
                if (isSelf) { v.x = fmaxf(v.x, 0.f); v.y = fmaxf(v.y, 0.f); }
                *reinterpret_cast<float2*>(outp + (size_t)rbase * ldo + c) = v;
            }
            if (rbase + 8 < M) {
                float2 v;
                v.x = acc[mt][nt][2] + b0;
                v.y = acc[mt][nt][3] + b1;
                if (isSelf) { v.x = fmaxf(v.x, 0.f); v.y = fmaxf(v.y, 0.f); }
                *reinterpret_cast<float2*>(outp + (size_t)(rbase + 8) * ldo + c) = v;
            }
        }
    }
}

// ---------------- final FC: ((A .* inv) [M x 256]) @ W[256 x 40] + bias ------
__global__ void __launch_bounds__(128)
fc_kernel(const float* __restrict__ A, const float* __restrict__ inv,
          const float* __restrict__ W, const float* __restrict__ bias,
          float* __restrict__ out, int M) {
    __shared__ float As[16][64];
    __shared__ float Ws[16][40];
    int t = threadIdx.x;
    int row0 = blockIdx.x * 64;
    int tr = t >> 3;  // 0..15 -> rows tr*4..tr*4+3
    int tc = t & 7;   // 0..7  -> cols tc*5..tc*5+4
    int ar = t >> 1;          // 0..63
    int ak = (t & 1) * 8;     // 0 or 8

    int rA = row0 + ar;
    float sc = (rA < M) ? inv[rA] : 0.f;

    float acc[4][5];
#pragma unroll
    for (int i = 0; i < 4; i++)
#pragma unroll
        for (int j = 0; j < 5; j++) acc[i][j] = 0.f;

    for (int k0 = 0; k0 < HD; k0 += 16) {
        {
            float4 u0 = make_float4(0.f, 0.f, 0.f, 0.f), u1 = u0;
            if (rA < M) {
                u0 = *reinterpret_cast<const float4*>(A + (size_t)rA * HD + k0 + ak);
                u1 = *reinterpret_cast<const float4*>(A + (size_t)rA * HD + k0 + ak + 4);
            }
            As[ak + 0][ar] = u0.x * sc; As[ak + 1][ar] = u0.y * sc;
            As[ak + 2][ar] = u0.z * sc; As[ak + 3][ar] = u0.w * sc;
            As[ak + 4][ar] = u1.x * sc; As[ak + 5][ar] = u1.y * sc;
            As[ak + 6][ar] = u1.z * sc; As[ak + 7][ar] = u1.w * sc;
        }
#pragma unroll
        for (int i = 0; i < 5; i++) {
            int idx = t + 128 * i;  // 0..639 = 16*40
            int kk = idx / 40, cc = idx - kk * 40;
            Ws[kk][cc] = W[(size_t)(k0 + kk) * NCLS + cc];
        }
        __syncthreads();
#pragma unroll
        for (int k = 0; k < 16; k++) {
            float4 av = *reinterpret_cast<const float4*>(&As[k][tr * 4]);
            float a[4] = {av.x, av.y, av.z, av.w};
            float w[5];
#pragma unroll
            for (int j = 0; j < 5; j++) w[j] = Ws[k][tc * 5 + j];
#pragma unroll
            for (int i = 0; i < 4; i++)
#pragma unroll
                for (int j = 0; j < 5; j++)
                    acc[i][j] = fmaf(a[i], w[j], acc[i][j]);
        }
        __syncthreads();
    }
#pragma unroll
    for (int i = 0; i < 4; i++) {
        int r = row0 + tr * 4 + i;
        if (r < M) {
#pragma unroll
            for (int j = 0; j < 5; j++)
                out[(size_t)r * NCLS + tc * 5 + j] = acc[i][j] + bias[tc * 5 + j];
        }
    }
}

// ---------------- launch ------------------------------------------------------
extern "C" void kernel_launch(void* const* d_in, const int* in_sizes, int n_in,
                              void* d_out, int out_size) {
    const float* x   = (const float*)d_in[0];
    const int*   src = (const int*)d_in[1];
    const int*   dst = (const int*)d_in[2];
    const float* w1s = (const float*)d_in[3];
    const float* b1s = (const float*)d_in[4];
    const float* w1n = (const float*)d_in[5];
    const float* b1n = (const float*)d_in[6];
    const float* w2s = (const float*)d_in[7];
    const float* b2s = (const float*)d_in[8];
    const float* w2n = (const float*)d_in[9];
    const float* b2n = (const float*)d_in[10];
    const float* wfc = (const float*)d_in[11];
    const float* bfc = (const float*)d_in[12];

    int N_ = in_sizes[0] / 128;
    int E_ = in_sizes[1];

    float *tbuf, *h1, *h2, *inv1, *inv2;
    int* degp;
    cudaGetSymbolAddress((void**)&tbuf, g_t);
    cudaGetSymbolAddress((void**)&h1, g_h1);
    cudaGetSymbolAddress((void**)&h2, g_h2);
    cudaGetSymbolAddress((void**)&inv1, g_inv1);
    cudaGetSymbolAddress((void**)&inv2, g_inv2);
    cudaGetSymbolAddress((void**)&degp, g_deg);

    int eblocks = (E_ + 255) / 256;
    int wblocks = (N_ * 32 + 255) / 256;   // warp-per-node kernels
    int gblocks = (N_ + 127) / 128;        // gemm row tiles

    // CSR build (per call; graph is an input)
    cudaMemsetAsync(degp, 0, (size_t)N_ * sizeof(int));
    count_kernel<<<eblocks, 256>>>(dst, E_);
    scan_kernel<<<1, 1024>>>(N_);
    scatter_kernel<<<eblocks, 256>>>(src, dst, E_);

    // ---- layer 1 ----  (Mean(x)@W == Mean(x@W): aggregate after GEMM)
    gemm_dual<<<gblocks, 512>>>(x, 128, nullptr, w1s, w1n, b1s,
                                h1, HD, tbuf, 128, N_, 128);
    agg_bias_relu_norm<<<wblocks, 256>>>(tbuf, b1n, h1, inv1, N_);

    // ---- layer 2 ----  (L2-normalize folded into A loads via inv1)
    gemm_dual<<<gblocks, 512>>>(h1, HD, inv1, w2s, w2n, b2s,
                                h2, HD, tbuf, 128, N_, 256);
    agg_bias_relu_norm<<<wblocks, 256>>>(tbuf, b2n, h2, inv2, N_);

    // ---- head ----
    fc_kernel<<<(N_ + 63) / 64, 128>>>(h2, inv2, wfc, bfc, (float*)d_out, N_);
}

// round 4
// speedup vs baseline: 1.9965x; 1.2365x over previous
#include <cuda_runtime.h>
#include <cuda_fp16.h>
#include <cstdint>

#define NMAX 100000
#define EMAX 1600000
#define HD   256      // concat hidden dim (2*128)
#define NCLS 40

// ---------------- scratch (static device globals; no allocation) -------------
__device__ __align__(16) int g_deg[NMAX];
__device__ int   g_rowptr[NMAX + 1];
__device__ int   g_cursor[NMAX];
__device__ int   g_esrc[EMAX];
__device__ int   g_bsum[128];
__device__ int   g_boff[128];
__device__ __align__(16) __half g_t[(size_t)NMAX * 128];  // fp16 pre-aggregation
__device__ float g_h1[(size_t)NMAX * HD];
__device__ float g_h2[(size_t)NMAX * HD];
__device__ float g_inv1[NMAX];
__device__ float g_inv2[NMAX];

// ---------------- tf32 / cp.async helpers -------------------------------------
__device__ __forceinline__ uint32_t f2tf32(float f) {
    uint32_t r;
    asm("cvt.rna.tf32.f32 %0, %1;" : "=r"(r) : "f"(f));
    return r;
}

__device__ __forceinline__ void mma_tf32(float& c0, float& c1, float& c2, float& c3,
                                         uint32_t a0, uint32_t a1, uint32_t a2, uint32_t a3,
                                         uint32_t b0, uint32_t b1) {
    asm volatile(
        "mma.sync.aligned.m16n8k8.row.col.f32.tf32.tf32.f32 "
        "{%0,%1,%2,%3}, {%4,%5,%6,%7}, {%8,%9}, {%0,%1,%2,%3};"
        : "+f"(c0), "+f"(c1), "+f"(c2), "+f"(c3)
        : "r"(a0), "r"(a1), "r"(a2), "r"(a3), "r"(b0), "r"(b1));
}

__device__ __forceinline__ void cp_async16(uint32_t dst, const void* src, bool pred) {
    int sz = pred ? 16 : 0;
    asm volatile("cp.async.cg.shared.global [%0], [%1], 16, %2;"
                 :: "r"(dst), "l"(src), "r"(sz));
}
__device__ __forceinline__ void cp_commit() {
    asm volatile("cp.async.commit_group;" ::: "memory");
}
__device__ __forceinline__ void cp_wait0() {
    asm volatile("cp.async.wait_group 0;" ::: "memory");
}

// ---------------- CSR build --------------------------------------------------
__global__ void count_kernel(const int* __restrict__ dst, int e) {
    int i = blockIdx.x * blockDim.x + threadIdx.x;
    if (i < e) atomicAdd(&g_deg[dst[i]], 1);
}

// pass 1: per-block (1024-elem chunk) sums of deg
__global__ void scan_block_sum(int n) {
    int b = blockIdx.x, t = threadIdx.x, lane = t & 31, w = t >> 5;
    int base = b * 1024 + t * 4;
    int s = 0;
    if (base + 3 < n) {
        int4 v = *reinterpret_cast<const int4*>(g_deg + base);
        s = v.x + v.y + v.z + v.w;
    } else {
#pragma unroll
        for (int j = 0; j < 4; j++) { int i = base + j; if (i < n) s += g_deg[i]; }
    }
#pragma unroll
    for (int off = 16; off; off >>= 1) s += __shfl_xor_sync(0xffffffffu, s, off);
    __shared__ int ws[8];
    if (lane == 0) ws[w] = s;
    __syncthreads();
    if (t == 0) {
        int tot = 0;
#pragma unroll
        for (int j = 0; j < 8; j++) tot += ws[j];
        g_bsum[b] = tot;
    }
}

// pass 2: exclusive scan of block sums (nb <= 128), also writes rowptr[n]
__global__ void scan_block_offsets(int nb, int n) {
    int t = threadIdx.x, lane = t & 31, w = t >> 5;
    int v = (t < nb) ? g_bsum[t] : 0;
    int val = v;
#pragma unroll
    for (int off = 1; off < 32; off <<= 1) {
        int u = __shfl_up_sync(0xffffffffu, val, off);
        if (lane >= off) val += u;
    }
    __shared__ int ws[4];
    if (lane == 31) ws[w] = val;
    __syncthreads();
    int add = 0;
#pragma unroll
    for (int j = 0; j < 4; j++) if (j < w) add += ws[j];
    int incl = val + add;
    if (t < nb) g_boff[t] = incl - v;
    if (t == nb - 1) g_rowptr[n] = incl;
}

// pass 3: per-chunk scan + global offset; writes rowptr & cursor
__global__ void scan_write(int n) {
    int b = blockIdx.x, t = threadIdx.x, lane = t & 31, w = t >> 5;
    int base = b * 1024 + t * 4;
    int4 v = make_int4(0, 0, 0, 0);
    if (base + 3 < n) v = *reinterpret_cast<const int4*>(g_deg + base);
    else {
        v.x = (base < n)     ? g_deg[base]     : 0;
        v.y = (base + 1 < n) ? g_deg[base + 1] : 0;
        v.z = (base + 2 < n) ? g_deg[base + 2] : 0;
        v.w = (base + 3 < n) ? g_deg[base + 3] : 0;
    }
    int s = v.x + v.y + v.z + v.w;
    int val = s;
#pragma unroll
    for (int off = 1; off < 32; off <<= 1) {
        int u = __shfl_up_sync(0xffffffffu, val, off);
        if (lane >= off) val += u;
    }
    __shared__ int ws[8];
    if (lane == 31) ws[w] = val;
    __syncthreads();
    int wadd = 0;
#pragma unroll
    for (int j = 0; j < 8; j++) if (j < w) wadd += ws[j];
    int e0 = g_boff[b] + wadd + (val - s);
    int e1 = e0 + v.x, e2 = e1 + v.y, e3 = e2 + v.z;
    if (base < n)     { g_rowptr[base]     = e0; g_cursor[base]     = e0; }
    if (base + 1 < n) { g_rowptr[base + 1] = e1; g_cursor[base + 1] = e1; }
    if (base + 2 < n) { g_rowptr[base + 2] = e2; g_cursor[base + 2] = e2; }
    if (base + 3 < n) { g_rowptr[base + 3] = e3; g_cursor[base + 3] = e3; }
}

__global__ void scatter_kernel(const int* __restrict__ src,
                               const int* __restrict__ dst, int e) {
    int i = blockIdx.x * blockDim.x + threadIdx.x;
    if (i < e) {
        int d = dst[i];
        int pos = atomicAdd(&g_cursor[d], 1);
        g_esrc[pos] = src[i];
    }
}

// ------ mean aggregation (fp16 rows) + bias + relu + fused row L2-invnorm ----
__device__ __forceinline__ void acc_h4(float4& a, uint2 u) {
    float2 f0 = __half22float2(*reinterpret_cast<__half2*>(&u.x));
    float2 f1 = __half22float2(*reinterpret_cast<__half2*>(&u.y));
    a.x += f0.x; a.y += f0.y; a.z += f1.x; a.w += f1.y;
}

__global__ void agg_bias_relu_norm(const __half* __restrict__ t, const float* __restrict__ bias,
                                   float* __restrict__ h, float* __restrict__ invn, int n) {
    int gw = (blockIdx.x * blockDim.x + threadIdx.x) >> 5;
    if (gw >= n) return;
    int lane = threadIdx.x & 31;
    int beg = g_rowptr[gw], end = g_rowptr[gw + 1];
    const uint2* tb = reinterpret_cast<const uint2*>(t);
    float4 acc = make_float4(0.f, 0.f, 0.f, 0.f);
    int e = beg;
    for (; e + 4 <= end; e += 4) {
        int s0 = g_esrc[e], s1 = g_esrc[e + 1], s2 = g_esrc[e + 2], s3 = g_esrc[e + 3];
        uint2 u0 = tb[(size_t)s0 * 32 + lane];
        uint2 u1 = tb[(size_t)s1 * 32 + lane];
        uint2 u2 = tb[(size_t)s2 * 32 + lane];
        uint2 u3 = tb[(size_t)s3 * 32 + lane];
        acc_h4(acc, u0); acc_h4(acc, u1); acc_h4(acc, u2); acc_h4(acc, u3);
    }
    for (; e < end; ++e) {
        uint2 u0 = tb[(size_t)g_esrc[e] * 32 + lane];
        acc_h4(acc, u0);
    }
    int cnt = end - beg;
    float inv = 1.0f / (float)(cnt > 0 ? cnt : 1);
    float4 b = *(reinterpret_cast<const float4*>(bias) + lane);
    float4 o;
    o.x = fmaxf(acc.x * inv + b.x, 0.f);
    o.y = fmaxf(acc.y * inv + b.y, 0.f);
    o.z = fmaxf(acc.z * inv + b.z, 0.f);
    o.w = fmaxf(acc.w * inv + b.w, 0.f);
    float4* row = reinterpret_cast<float4*>(h + (size_t)gw * HD);
    row[32 + lane] = o;                       // neigh half
    float4 s4 = row[lane];                    // self half (written by GEMM)
    float s = s4.x * s4.x + s4.y * s4.y + s4.z * s4.z + s4.w * s4.w +
              o.x * o.x + o.y * o.y + o.z * o.z + o.w * o.w;
#pragma unroll
    for (int off = 16; off; off >>= 1) s += __shfl_xor_sync(0xffffffffu, s, off);
    if (lane == 0) invn[gw] = 1.0f / fmaxf(sqrtf(s), 1e-12f);
}

// ---- fused dual-output tf32 GEMM (cp.async pipeline, conflict-free smem):
//   out1[M x 128] = relu(rowScale .* (A @ W1) + bias1)   (self branch, fp32)
//   out2[M x 128] =      rowScale .* (A @ W2)            (neighbor branch, fp16)
// BM=128, BN=256, BK=16, 512 threads, warp grid 4m x 4n, warp tile 32x64.
#define PAD_A 20
#define PAD_B 264

__global__ void __launch_bounds__(512)
gemm_dual(const float* __restrict__ A, int lda, const float* __restrict__ rowScale,
          const float* __restrict__ W1, const float* __restrict__ W2,
          const float* __restrict__ bias1,
          float* __restrict__ out1, int ldo1, __half* __restrict__ out2, int ldo2,
          int M, int K) {
    __shared__ __align__(16) float As[2][128][PAD_A];  // [m][k] raw fp32, padded
    __shared__ __align__(16) float Bs[2][16][PAD_B];   // [k][n] raw fp32, padded

    const int t = threadIdx.x;
    const int warp = t >> 5, lane = t & 31;
    const int wm = warp & 3, wn = warp >> 2;   // 4 x 4 warp grid
    const int grp = lane >> 2, qid = lane & 3;
    const int row0 = blockIdx.x * 128;

    const int ar = t >> 2;          // 0..127
    const int ac = (t & 3) << 2;    // 0,4,8,12
    const int gr = row0 + ar;
    const bool arOK = (gr < M);

    float acc[2][8][4];
#pragma unroll
    for (int i = 0; i < 2; i++)
#pragma unroll
        for (int j = 0; j < 8; j++)
#pragma unroll
            for (int c = 0; c < 4; c++) acc[i][j][c] = 0.f;

    auto issue = [&](int tile, int st) {
        int k0 = tile * 16;
        cp_async16((uint32_t)__cvta_generic_to_shared(&As[st][ar][ac]),
                   A + (size_t)gr * lda + k0 + ac, arOK);
#pragma unroll
        for (int i = 0; i < 2; i++) {
            int idx = t + 512 * i;          // 1024 16B chunks
            int kk = idx >> 6;              // 0..15
            int nn = (idx & 63) << 2;       // 0..252
            const float* src = (nn < 128)
                ? (W1 + (size_t)(k0 + kk) * 128 + nn)
                : (W2 + (size_t)(k0 + kk) * 128 + (nn - 128));
            cp_async16((uint32_t)__cvta_generic_to_shared(&Bs[st][kk][nn]), src, true);
        }
        cp_commit();
    };

    issue(0, 0);
    cp_wait0();
    __syncthreads();

    const int nT = K / 16;
    int cur = 0;
    for (int tile = 0; tile < nT; ++tile) {
        bool has = (tile + 1 < nT);
        if (has) issue(tile + 1, cur ^ 1);
#pragma unroll
        for (int s = 0; s < 2; ++s) {
            const int k8 = s * 8;
            uint32_t af[2][4], bf[8][2];
#pragma unroll
            for (int mt = 0; mt < 2; ++mt) {
                int m = wm * 32 + mt * 16 + grp;
                af[mt][0] = f2tf32(As[cur][m][k8 + qid]);
                af[mt][1] = f2tf32(As[cur][m + 8][k8 + qid]);
                af[mt][2] = f2tf32(As[cur][m][k8 + qid + 4]);
                af[mt][3] = f2tf32(As[cur][m + 8][k8 + qid + 4]);
            }
#pragma unroll
            for (int nt = 0; nt < 8; ++nt) {
                int nidx = wn * 64 + nt * 8 + grp;
                bf[nt][0] = f2tf32(Bs[cur][k8 + qid][nidx]);
                bf[nt][1] = f2tf32(Bs[cur][k8 + qid + 4][nidx]);
            }
#pragma unroll
            for (int mt = 0; mt < 2; ++mt)
#pragma unroll
                for (int nt = 0; nt < 8; ++nt)
                    mma_tf32(acc[mt][nt][0], acc[mt][nt][1], acc[mt][nt][2], acc[mt][nt][3],
                             af[mt][0], af[mt][1], af[mt][2], af[mt][3],
                             bf[nt][0], bf[nt][1]);
        }
        if (has) cp_wait0();
        __syncthreads();
        cur ^= 1;
    }

    // epilogue: rowScale applied here (diag(s)A@W == (A.*s)@W up to tf32 rounding)
#pragma unroll
    for (int mt = 0; mt < 2; ++mt) {
        int rbase = row0 + wm * 32 + mt * 16 + grp;
        float sc0 = 1.f, sc1 = 1.f;
        if (rowScale != nullptr) {
            if (rbase < M)     sc0 = rowScale[rbase];
            if (rbase + 8 < M) sc1 = rowScale[rbase + 8];
        }
#pragma unroll
        for (int nt = 0; nt < 8; ++nt) {
            int col = wn * 64 + nt * 8 + qid * 2;
            if (col < 128) {
                float b0 = bias1[col], b1 = bias1[col + 1];
                if (rbase < M) {
                    float2 v;
                    v.x = fmaxf(acc[mt][nt][0] * sc0 + b0, 0.f);
                    v.y = fmaxf(acc[mt][nt][1] * sc0 + b1, 0.f);
                    *reinterpret_cast<float2*>(out1 + (size_t)rbase * ldo1 + col) = v;
                }
                if (rbase + 8 < M) {
                    float2 v;
                    v.x = fmaxf(acc[mt][nt][2] * sc1 + b0, 0.f);
                    v.y = fmaxf(acc[mt][nt][3] * sc1 + b1, 0.f);
                    *reinterpret_cast<float2*>(out1 + (size_t)(rbase + 8) * ldo1 + col) = v;
                }
            } else {
                int c = col - 128;
                if (rbase < M) {
                    __half2 hv = __floats2half2_rn(acc[mt][nt][0] * sc0, acc[mt][nt][1] * sc0);
                    *reinterpret_cast<__half2*>(out2 + (size_t)rbase * ldo2 + c) = hv;
                }
                if (rbase + 8 < M) {
                    __half2 hv = __floats2half2_rn(acc[mt][nt][2] * sc1, acc[mt][nt][3] * sc1);
                    *reinterpret_cast<__half2*>(out2 + (size_t)(rbase + 8) * ldo2 + c) = hv;
                }
            }
        }
    }
}

// ---------------- final FC: ((A .* inv) [M x 256]) @ W[256 x 40] + bias ------
__global__ void __launch_bounds__(128)
fc_kernel(const float* __restrict__ A, const float* __restrict__ inv,
          const float* __restrict__ W, const float* __restrict__ bias,
          float* __restrict__ out, int M) {
    __shared__ float As[16][64];
    __shared__ float Ws[16][40];
    int t = threadIdx.x;
    int row0 = blockIdx.x * 64;
    int tr = t >> 3;  // 0..15 -> rows tr*4..tr*4+3
    int tc = t & 7;   // 0..7  -> cols tc*5..tc*5+4
    int ar = t >> 1;          // 0..63
    int ak = (t & 1) * 8;     // 0 or 8

    int rA = row0 + ar;
    float sc = (rA < M) ? inv[rA] : 0.f;

    float acc[4][5];
#pragma unroll
    for (int i = 0; i < 4; i++)
#pragma unroll
        for (int j = 0; j < 5; j++) acc[i][j] = 0.f;

    for (int k0 = 0; k0 < HD; k0 += 16) {
        {
            float4 u0 = make_float4(0.f, 0.f, 0.f, 0.f), u1 = u0;
            if (rA < M) {
                u0 = *reinterpret_cast<const float4*>(A + (size_t)rA * HD + k0 + ak);
                u1 = *reinterpret_cast<const float4*>(A + (size_t)rA * HD + k0 + ak + 4);
            }
            As[ak + 0][ar] = u0.x * sc; As[ak + 1][ar] = u0.y * sc;
            As[ak + 2][ar] = u0.z * sc; As[ak + 3][ar] = u0.w * sc;
            As[ak + 4][ar] = u1.x * sc; As[ak + 5][ar] = u1.y * sc;
            As[ak + 6][ar] = u1.z * sc; As[ak + 7][ar] = u1.w * sc;
        }
#pragma unroll
        for (int i = 0; i < 5; i++) {
            int idx = t + 128 * i;  // 0..639 = 16*40
            int kk = idx / 40, cc = idx - kk * 40;
            Ws[kk][cc] = W[(size_t)(k0 + kk) * NCLS + cc];
        }
        __syncthreads();
#pragma unroll
        for (int k = 0; k < 16; k++) {
            float4 av = *reinterpret_cast<const float4*>(&As[k][tr * 4]);
            float a[4] = {av.x, av.y, av.z, av.w};
            float w[5];
#pragma unroll
            for (int j = 0; j < 5; j++) w[j] = Ws[k][tc * 5 + j];
#pragma unroll
            for (int i = 0; i < 4; i++)
#pragma unroll
                for (int j = 0; j < 5; j++)
                    acc[i][j] = fmaf(a[i], w[j], acc[i][j]);
        }
        __syncthreads();
    }
#pragma unroll
    for (int i = 0; i < 4; i++) {
        int r = row0 + tr * 4 + i;
        if (r < M) {
#pragma unroll
            for (int j = 0; j < 5; j++)
                out[(size_t)r * NCLS + tc * 5 + j] = acc[i][j] + bias[tc * 5 + j];
        }
    }
}

// ---------------- launch ------------------------------------------------------
extern "C" void kernel_launch(void* const* d_in, const int* in_sizes, int n_in,
                              void* d_out, int out_size) {
    const float* x   = (const float*)d_in[0];
    const int*   src = (const int*)d_in[1];
    const int*   dst = (const int*)d_in[2];
    const float* w1s = (const float*)d_in[3];
    const float* b1s = (const float*)d_in[4];
    const float* w1n = (const float*)d_in[5];
    const float* b1n = (const float*)d_in[6];
    const float* w2s = (const float*)d_in[7];
    const float* b2s = (const float*)d_in[8];
    const float* w2n = (const float*)d_in[9];
    const float* b2n = (const float*)d_in[10];
    const float* wfc = (const float*)d_in[11];
    const float* bfc = (const float*)d_in[12];

    int N_ = in_sizes[0] / 128;
    int E_ = in_sizes[1];

    __half* tbuf;
    float *h1, *h2, *inv1, *inv2;
    int* degp;
    cudaGetSymbolAddress((void**)&tbuf, g_t);
    cudaGetSymbolAddress((void**)&h1, g_h1);
    cudaGetSymbolAddress((void**)&h2, g_h2);
    cudaGetSymbolAddress((void**)&inv1, g_inv1);
    cudaGetSymbolAddress((void**)&inv2, g_inv2);
    cudaGetSymbolAddress((void**)&degp, g_deg);

    int eblocks = (E_ + 255) / 256;
    int wblocks = (N_ * 32 + 255) / 256;   // warp-per-node kernels
    int gblocks = (N_ + 127) / 128;        // gemm row tiles
    int nb = (N_ + 1023) / 1024;           // scan chunks

    // CSR build (per call; graph is an input)
    cudaMemsetAsync(degp, 0, (size_t)N_ * sizeof(int));
    count_kernel<<<eblocks, 256>>>(dst, E_);
    scan_block_sum<<<nb, 256>>>(N_);
    scan_block_offsets<<<1, 128>>>(nb, N_);
    scan_write<<<nb, 256>>>(N_);
    scatter_kernel<<<eblocks, 256>>>(src, dst, E_);

    // ---- layer 1 ----  (Mean(x)@W == Mean(x@W): aggregate after GEMM)
    gemm_dual<<<gblocks, 512>>>(x, 128, nullptr, w1s, w1n, b1s,
                                h1, HD, tbuf, 128, N_, 128);
    agg_bias_relu_norm<<<wblocks, 256>>>(tbuf, b1n, h1, inv1, N_);

    // ---- layer 2 ----  (L2-normalize folded into GEMM epilogue via inv1)
    gemm_dual<<<gblocks, 512>>>(h1, HD, inv1, w2s, w2n, b2s,
                                h2, HD, tbuf, 128, N_, 256);
    agg_bias_relu_norm<<<wblocks, 256>>>(tbuf, b2n, h2, inv2, N_);

    // ---- head ----
    fc_kernel<<<(N_ + 63) / 64, 128>>>(h2, inv2, wfc, bfc, (float*)d_out, N_);
}

// round 5
// speedup vs baseline: 2.4419x; 1.2231x over previous
#include <cuda_runtime.h>
#include <cuda_fp16.h>
#include <cstdint>

#define NMAX 100000
#define EMAX 1600000
#define HD   256      // concat hidden dim (2*128)
#define NCLS 40
#define PAD  24       // smem row stride in halves (48B, conflict-free, 16B-aligned)
#define STAGES 3

// ---------------- scratch (static device globals; no allocation) -------------
__device__ __align__(16) int g_deg[NMAX];
__device__ int   g_rowptr[NMAX + 1];
__device__ int   g_cursor[NMAX];
__device__ int   g_esrc[EMAX];
__device__ int   g_bsum[128];
__device__ int   g_boff[128];
__device__ __align__(16) __half g_t[(size_t)NMAX * 128];   // neighbor pre-agg
__device__ __align__(16) __half g_xh[(size_t)NMAX * 128];  // x in fp16
__device__ __align__(16) __half g_h1[(size_t)NMAX * HD];   // fp16 [self|neigh]
__device__ __align__(16) __half g_h2[(size_t)NMAX * HD];
__device__ __align__(16) __half g_wt1[256 * 128];          // layer1 W^T fp16 [n][k]
__device__ __align__(16) __half g_wt2[256 * 256];          // layer2 W^T fp16 [n][k]
__device__ float g_inv1[NMAX];
__device__ float g_inv2[NMAX];

// ---------------- mma / cp.async helpers --------------------------------------
__device__ __forceinline__ void mma_f16(float& c0, float& c1, float& c2, float& c3,
                                        uint32_t a0, uint32_t a1, uint32_t a2, uint32_t a3,
                                        uint32_t b0, uint32_t b1) {
    asm volatile(
        "mma.sync.aligned.m16n8k16.row.col.f32.f16.f16.f32 "
        "{%0,%1,%2,%3}, {%4,%5,%6,%7}, {%8,%9}, {%0,%1,%2,%3};"
        : "+f"(c0), "+f"(c1), "+f"(c2), "+f"(c3)
        : "r"(a0), "r"(a1), "r"(a2), "r"(a3), "r"(b0), "r"(b1));
}

__device__ __forceinline__ void ldsm_x4(uint32_t* r, uint32_t addr) {
    asm volatile("ldmatrix.sync.aligned.m8n8.x4.shared.b16 {%0,%1,%2,%3}, [%4];"
                 : "=r"(r[0]), "=r"(r[1]), "=r"(r[2]), "=r"(r[3]) : "r"(addr));
}

__device__ __forceinline__ void cp_async16(uint32_t dst, const void* src, bool pred) {
    int sz = pred ? 16 : 0;
    asm volatile("cp.async.cg.shared.global [%0], [%1], 16, %2;"
                 :: "r"(dst), "l"(src), "r"(sz));
}
__device__ __forceinline__ void cp_commit() {
    asm volatile("cp.async.commit_group;" ::: "memory");
}
template <int N>
__device__ __forceinline__ void cp_wait() {
    asm volatile("cp.async.wait_group %0;" :: "n"(N) : "memory");
}

// ---------------- CSR build --------------------------------------------------
__global__ void count_kernel(const int* __restrict__ dst, int e) {
    int i = blockIdx.x * blockDim.x + threadIdx.x;
    if (i < e) atomicAdd(&g_deg[dst[i]], 1);
}

__global__ void scan_block_sum(int n) {
    int b = blockIdx.x, t = threadIdx.x, lane = t & 31, w = t >> 5;
    int base = b * 1024 + t * 4;
    int s = 0;
    if (base + 3 < n) {
        int4 v = *reinterpret_cast<const int4*>(g_deg + base);
        s = v.x + v.y + v.z + v.w;
    } else {
#pragma unroll
        for (int j = 0; j < 4; j++) { int i = base + j; if (i < n) s += g_deg[i]; }
    }
#pragma unroll
    for (int off = 16; off; off >>= 1) s += __shfl_xor_sync(0xffffffffu, s, off);
    __shared__ int ws[8];
    if (lane == 0) ws[w] = s;
    __syncthreads();
    if (t == 0) {
        int tot = 0;
#pragma unroll
        for (int j = 0; j < 8; j++) tot += ws[j];
        g_bsum[b] = tot;
    }
}

__global__ void scan_block_offsets(int nb, int n) {
    int t = threadIdx.x, lane = t & 31, w = t >> 5;
    int v = (t < nb) ? g_bsum[t] : 0;
    int val = v;
#pragma unroll
    for (int off = 1; off < 32; off <<= 1) {
        int u = __shfl_up_sync(0xffffffffu, val, off);
        if (lane >= off) val += u;
    }
    __shared__ int ws[4];
    if (lane == 31) ws[w] = val;
    __syncthreads();
    int add = 0;
#pragma unroll
    for (int j = 0; j < 4; j++) if (j < w) add += ws[j];
    int incl = val + add;
    if (t < nb) g_boff[t] = incl - v;
    if (t == nb - 1) g_rowptr[n] = incl;
}

__global__ void scan_write(int n) {
    int b = blockIdx.x, t = threadIdx.x, lane = t & 31, w = t >> 5;
    int base = b * 1024 + t * 4;
    int4 v = make_int4(0, 0, 0, 0);
    if (base + 3 < n) v = *reinterpret_cast<const int4*>(g_deg + base);
    else {
        v.x = (base < n)     ? g_deg[base]     : 0;
        v.y = (base + 1 < n) ? g_deg[base + 1] : 0;
        v.z = (base + 2 < n) ? g_deg[base + 2] : 0;
        v.w = (base + 3 < n) ? g_deg[base + 3] : 0;
    }
    int s = v.x + v.y + v.z + v.w;
    int val = s;
#pragma unroll
    for (int off = 1; off < 32; off <<= 1) {
        int u = __shfl_up_sync(0xffffffffu, val, off);
        if (lane >= off) val += u;
    }
    __shared__ int ws[8];
    if (lane == 31) ws[w] = val;
    __syncthreads();
    int wadd = 0;
#pragma unroll
    for (int j = 0; j < 8; j++) if (j < w) wadd += ws[j];
    int e0 = g_boff[b] + wadd + (val - s);
    int e1 = e0 + v.x, e2 = e1 + v.y, e3 = e2 + v.z;
    if (base < n)     { g_rowptr[base]     = e0; g_cursor[base]     = e0; }
    if (base + 1 < n) { g_rowptr[base + 1] = e1; g_cursor[base + 1] = e1; }
    if (base + 2 < n) { g_rowptr[base + 2] = e2; g_cursor[base + 2] = e2; }
    if (base + 3 < n) { g_rowptr[base + 3] = e3; g_cursor[base + 3] = e3; }
}

__global__ void scatter_kernel(const int* __restrict__ src,
                               const int* __restrict__ dst, int e) {
    int i = blockIdx.x * blockDim.x + threadIdx.x;
    if (i < e) {
        int d = dst[i];
        int pos = atomicAdd(&g_cursor[d], 1);
        g_esrc[pos] = src[i];
    }
}

// ---------------- fp16 conversions -------------------------------------------
__global__ void x_to_half(const float* __restrict__ x, __half* __restrict__ xh, int n4) {
    int i = blockIdx.x * blockDim.x + threadIdx.x;
    if (i < n4) {
        float4 v = reinterpret_cast<const float4*>(x)[i];
        __half2 p0 = __floats2half2_rn(v.x, v.y);
        __half2 p1 = __floats2half2_rn(v.z, v.w);
        uint2 u;
        u.x = *reinterpret_cast<uint32_t*>(&p0);
        u.y = *reinterpret_cast<uint32_t*>(&p1);
        reinterpret_cast<uint2*>(xh)[i] = u;
    }
}

// combined transposed weights: Wt[n][k], n<128 from W1, n>=128 from W2 (each [k][128])
__global__ void w_to_half_t(const float* __restrict__ W1, const float* __restrict__ W2,
                            __half* __restrict__ Wt, int K) {
    int idx = blockIdx.x * blockDim.x + threadIdx.x;
    if (idx < 256 * K) {
        int n = idx / K, k = idx - n * K;
        float v = (n < 128) ? W1[(size_t)k * 128 + n] : W2[(size_t)k * 128 + (n - 128)];
        Wt[idx] = __float2half_rn(v);
    }
}

// ------ mean aggregation (fp16) + bias + relu + fused row L2-invnorm ---------
__device__ __forceinline__ void acc_h4(float4& a, uint2 u) {
    float2 f0 = __half22float2(*reinterpret_cast<__half2*>(&u.x));
    float2 f1 = __half22float2(*reinterpret_cast<__half2*>(&u.y));
    a.x += f0.x; a.y += f0.y; a.z += f1.x; a.w += f1.y;
}

__global__ void agg_bias_relu_norm(const __half* __restrict__ t, const float* __restrict__ bias,
                                   __half* __restrict__ h, float* __restrict__ invn, int n) {
    int gw = (blockIdx.x * blockDim.x + threadIdx.x) >> 5;
    if (gw >= n) return;
    int lane = threadIdx.x & 31;
    int beg = g_rowptr[gw], end = g_rowptr[gw + 1];
    const uint2* tb = reinterpret_cast<const uint2*>(t);
    float4 acc = make_float4(0.f, 0.f, 0.f, 0.f);
    int e = beg;
    for (; e + 4 <= end; e += 4) {
        int s0 = g_esrc[e], s1 = g_esrc[e + 1], s2 = g_esrc[e + 2], s3 = g_esrc[e + 3];
        uint2 u0 = tb[(size_t)s0 * 32 + lane];
        uint2 u1 = tb[(size_t)s1 * 32 + lane];
        uint2 u2 = tb[(size_t)s2 * 32 + lane];
        uint2 u3 = tb[(size_t)s3 * 32 + lane];
        acc_h4(acc, u0); acc_h4(acc, u1); acc_h4(acc, u2); acc_h4(acc, u3);
    }
    for (; e < end; ++e) {
        uint2 u0 = tb[(size_t)g_esrc[e] * 32 + lane];
        acc_h4(acc, u0);
    }
    int cnt = end - beg;
    float inv = 1.0f / (float)(cnt > 0 ? cnt : 1);
    float4 b = *(reinterpret_cast<const float4*>(bias) + lane);
    float4 o;
    o.x = fmaxf(acc.x * inv + b.x, 0.f);
    o.y = fmaxf(acc.y * inv + b.y, 0.f);
    o.z = fmaxf(acc.z * inv + b.z, 0.f);
    o.w = fmaxf(acc.w * inv + b.w, 0.f);
    __half* row = h + (size_t)gw * HD;
    __half2 p0 = __floats2half2_rn(o.x, o.y);
    __half2 p1 = __floats2half2_rn(o.z, o.w);
    uint2 w;
    w.x = *reinterpret_cast<uint32_t*>(&p0);
    w.y = *reinterpret_cast<uint32_t*>(&p1);
    reinterpret_cast<uint2*>(row + 128)[lane] = w;          // neigh half
    uint2 sv = reinterpret_cast<const uint2*>(row)[lane];   // self half (from GEMM)
    float2 s0 = __half22float2(*reinterpret_cast<__half2*>(&sv.x));
    float2 s1 = __half22float2(*reinterpret_cast<__half2*>(&sv.y));
    float s = s0.x * s0.x + s0.y * s0.y + s1.x * s1.x + s1.y * s1.y +
              o.x * o.x + o.y * o.y + o.z * o.z + o.w * o.w;
#pragma unroll
    for (int off = 16; off; off >>= 1) s += __shfl_xor_sync(0xffffffffu, s, off);
    if (lane == 0) invn[gw] = 1.0f / fmaxf(sqrtf(s), 1e-12f);
}

// ---- fused dual-output fp16 GEMM (3-stage cp.async + ldmatrix + m16n8k16):
//   out1[:,0:128] = relu(rowScale .* (A @ W[:,0:128]) + bias1)   (fp16, ld=ldo1)
//   out2          =      rowScale .* (A @ W[:,128:256])          (fp16, ld=ldo2)
// A: [M x lda] fp16 row-major; Wt: [256 x K] fp16 (transposed, n-major).
// BM=128, BN=256, BK=16, 512 threads, warp grid 4m x 4n, warp tile 32x64.
__global__ void __launch_bounds__(512)
gemm_dual_h(const __half* __restrict__ A, int lda, const float* __restrict__ rowScale,
            const __half* __restrict__ Wt, const float* __restrict__ bias1,
            __half* __restrict__ out1, int ldo1, __half* __restrict__ out2, int ldo2,
            int M, int K) {
    __shared__ __align__(16) __half As[STAGES][128][PAD];
    __shared__ __align__(16) __half Bs[STAGES][256][PAD];

    const int t = threadIdx.x;
    const int warp = t >> 5, lane = t & 31;
    const int wm = warp & 3, wn = warp >> 2;   // 4 x 4 warp grid
    const int grp = lane >> 2, qid = lane & 3;
    const int row0 = blockIdx.x * 128;

    const uint32_t asb = (uint32_t)__cvta_generic_to_shared(&As[0][0][0]);
    const uint32_t bsb = (uint32_t)__cvta_generic_to_shared(&Bs[0][0][0]);

    float acc[2][8][4];
#pragma unroll
    for (int i = 0; i < 2; i++)
#pragma unroll
        for (int j = 0; j < 8; j++)
#pragma unroll
            for (int c = 0; c < 4; c++) acc[i][j][c] = 0.f;

    auto issue = [&](int tile, int st) {
        int k0 = tile * 16;
        if (t < 256) {                       // A: 128 rows x 2 16B chunks
            int row = t >> 1, hf = t & 1;
            int gr = row0 + row;
            cp_async16(asb + (uint32_t)(((st * 128 + row) * PAD + hf * 8) * 2),
                       A + (size_t)gr * lda + k0 + hf * 8, gr < M);
        }
        {                                    // B: 256 rows x 2 16B chunks
            int nrow = t >> 1, hf = t & 1;
            cp_async16(bsb + (uint32_t)(((st * 256 + nrow) * PAD + hf * 8) * 2),
                       Wt + (size_t)nrow * K + k0 + hf * 8, true);
        }
        cp_commit();
    };

    const int nT = K / 16;   // >= 2 always (K = 128 or 256)
    issue(0, 0);
    issue(1, 1);
    cp_wait<1>();
    __syncthreads();

    for (int tile = 0; tile < nT; ++tile) {
        int cur = tile % STAGES;
        // fragment loads via ldmatrix (conflict-free at 48B row stride)
        uint32_t af[2][4], bq[4][4];
#pragma unroll
        for (int mt = 0; mt < 2; ++mt) {
            int m0 = wm * 32 + mt * 16;
            int arow = m0 + (lane & 15);
            int acol = (lane >> 4) * 8;
            ldsm_x4(af[mt], asb + (uint32_t)(((cur * 128 + arow) * PAD + acol) * 2));
        }
#pragma unroll
        for (int np = 0; np < 4; ++np) {
            int n0 = wn * 64 + np * 16;
            int brow = n0 + ((lane >> 4) << 3) + (lane & 7);
            int bcol = ((lane >> 3) & 1) * 8;
            ldsm_x4(bq[np], bsb + (uint32_t)(((cur * 256 + brow) * PAD + bcol) * 2));
        }
#pragma unroll
        for (int mt = 0; mt < 2; ++mt)
#pragma unroll
            for (int nt = 0; nt < 8; ++nt)
                mma_f16(acc[mt][nt][0], acc[mt][nt][1], acc[mt][nt][2], acc[mt][nt][3],
                        af[mt][0], af[mt][1], af[mt][2], af[mt][3],
                        bq[nt >> 1][(nt & 1) * 2], bq[nt >> 1][(nt & 1) * 2 + 1]);

        if (tile + 2 < nT) {
            issue(tile + 2, (tile + 2) % STAGES);
            cp_wait<1>();
        } else {
            cp_wait<0>();
        }
        __syncthreads();
    }

    // epilogue: rowScale applied post-GEMM (diag(s)(A@W) == (A.*s)@W)
#pragma unroll
    for (int mt = 0; mt < 2; ++mt) {
        int rbase = row0 + wm * 32 + mt * 16 + grp;
        float sc0 = 1.f, sc1 = 1.f;
        if (rowScale != nullptr) {
            if (rbase < M)     sc0 = rowScale[rbase];
            if (rbase + 8 < M) sc1 = rowScale[rbase + 8];
        }
#pragma unroll
        for (int nt = 0; nt < 8; ++nt) {
            int col = wn * 64 + nt * 8 + qid * 2;
            if (col < 128) {
                float b0 = bias1[col], b1 = bias1[col + 1];
                if (rbase < M) {
                    __half2 hv = __floats2half2_rn(fmaxf(acc[mt][nt][0] * sc0 + b0, 0.f),
                                                   fmaxf(acc[mt][nt][1] * sc0 + b1, 0.f));
                    *reinterpret_cast<__half2*>(out1 + (size_t)rbase * ldo1 + col) = hv;
                }
                if (rbase + 8 < M) {
                    __half2 hv = __floats2half2_rn(fmaxf(acc[mt][nt][2] * sc1 + b0, 0.f),
                                                   fmaxf(acc[mt][nt][3] * sc1 + b1, 0.f));
                    *reinterpret_cast<__half2*>(out1 + (size_t)(rbase + 8) * ldo1 + col) = hv;
                }
            } else {
                int c = col - 128;
                if (rbase < M) {
                    __half2 hv = __floats2half2_rn(acc[mt][nt][0] * sc0, acc[mt][nt][1] * sc0);
                    *reinterpret_cast<__half2*>(out2 + (size_t)rbase * ldo2 + c) = hv;
                }
                if (rbase + 8 < M) {
                    __half2 hv = __floats2half2_rn(acc[mt][nt][2] * sc1, acc[mt][nt][3] * sc1);
                    *reinterpret_cast<__half2*>(out2 + (size_t)(rbase + 8) * ldo2 + c) = hv;
                }
            }
        }
    }
}

// ---------------- final FC: ((A .* inv) [M x 256] fp16) @ W[256 x 40] + bias --
__global__ void __launch_bounds__(128)
fc_kernel(const __half* __restrict__ A, const float* __restrict__ inv,
          const float* __restrict__ W, const float* __restrict__ bias,
          float* __restrict__ out, int M) {
    __shared__ float As[16][64];
    __shared__ float Ws[16][40];
    int t = threadIdx.x;
    int row0 = blockIdx.x * 64;
    int tr = t >> 3;  // 0..15 -> rows tr*4..tr*4+3
    int tc = t & 7;   // 0..7  -> cols tc*5..tc*5+4
    int ar = t >> 1;          // 0..63
    int ak = (t & 1) * 8;     // 0 or 8

    int rA = row0 + ar;
    float sc = (rA < M) ? inv[rA] : 0.f;

    float acc[4][5];
#pragma unroll
    for (int i = 0; i < 4; i++)
#pragma unroll
        for (int j = 0; j < 5; j++) acc[i][j] = 0.f;

    for (int k0 = 0; k0 < HD; k0 += 16) {
        {
            float f[8] = {0.f, 0.f, 0.f, 0.f, 0.f, 0.f, 0.f, 0.f};
            if (rA < M) {
                uint4 u = *reinterpret_cast<const uint4*>(A + (size_t)rA * HD + k0 + ak);
                float2 p0 = __half22float2(*reinterpret_cast<__half2*>(&u.x));
                float2 p1 = __half22float2(*reinterpret_cast<__half2*>(&u.y));
                float2 p2 = __half22float2(*reinterpret_cast<__half2*>(&u.z));
                float2 p3 = __half22float2(*reinterpret_cast<__half2*>(&u.w));
                f[0] = p0.x; f[1] = p0.y; f[2] = p1.x; f[3] = p1.y;
                f[4] = p2.x; f[5] = p2.y; f[6] = p3.x; f[7] = p3.y;
            }
#pragma unroll
            for (int j = 0; j < 8; j++) As[ak + j][ar] = f[j] * sc;
        }
#pragma unroll
        for (int i = 0; i < 5; i++) {
            int idx = t + 128 * i;  // 0..639 = 16*40
            int kk = idx / 40, cc = idx - kk * 40;
            Ws[kk][cc] = W[(size_t)(k0 + kk) * NCLS + cc];
        }
        __syncthreads();
#pragma unroll
        for (int k = 0; k < 16; k++) {
            float4 av = *reinterpret_cast<const float4*>(&As[k][tr * 4]);
            float a[4] = {av.x, av.y, av.z, av.w};
            float w[5];
#pragma unroll
            for (int j = 0; j < 5; j++) w[j] = Ws[k][tc * 5 + j];
#pragma unroll
            for (int i = 0; i < 4; i++)
#pragma unroll
                for (int j = 0; j < 5; j++)
                    acc[i][j] = fmaf(a[i], w[j], acc[i][j]);
        }
        __syncthreads();
    }
#pragma unroll
    for (int i = 0; i < 4; i++) {
        int r = row0 + tr * 4 + i;
        if (r < M) {
#pragma unroll
            for (int j = 0; j < 5; j++)
                out[(size_t)r * NCLS + tc * 5 + j] = acc[i][j] + bias[tc * 5 + j];
        }
    }
}

// ---------------- launch ------------------------------------------------------
extern "C" void kernel_launch(void* const* d_in, const int* in_sizes, int n_in,
                              void* d_out, int out_size) {
    const float* x   = (const float*)d_in[0];
    const int*   src = (const int*)d_in[1];
    const int*   dst = (const int*)d_in[2];
    const float* w1s = (const float*)d_in[3];
    const float* b1s = (const float*)d_in[4];
    const float* w1n = (const float*)d_in[5];
    const float* b1n = (const float*)d_in[6];
    const float* w2s = (const float*)d_in[7];
    const float* b2s = (const float*)d_in[8];
    const float* w2n = (const float*)d_in[9];
    const float* b2n = (const float*)d_in[10];
    const float* wfc = (const float*)d_in[11];
    const float* bfc = (const float*)d_in[12];

    int N_ = in_sizes[0] / 128;
    int E_ = in_sizes[1];

    __half *tbuf, *xh, *h1, *h2, *wt1, *wt2;
    float *inv1, *inv2;
    int* degp;
    cudaGetSymbolAddress((void**)&tbuf, g_t);
    cudaGetSymbolAddress((void**)&xh, g_xh);
    cudaGetSymbolAddress((void**)&h1, g_h1);
    cudaGetSymbolAddress((void**)&h2, g_h2);
    cudaGetSymbolAddress((void**)&wt1, g_wt1);
    cudaGetSymbolAddress((void**)&wt2, g_wt2);
    cudaGetSymbolAddress((void**)&inv1, g_inv1);
    cudaGetSymbolAddress((void**)&inv2, g_inv2);
    cudaGetSymbolAddress((void**)&degp, g_deg);

    int eblocks = (E_ + 255) / 256;
    int wblocks = (N_ * 32 + 255) / 256;   // warp-per-node kernels
    int gblocks = (N_ + 127) / 128;        // gemm row tiles
    int nb = (N_ + 1023) / 1024;           // scan chunks

    // input conversions (weights tiny; x one pass)
    x_to_half<<<(N_ * 32 + 255) / 256, 256>>>(x, xh, N_ * 32);
    w_to_half_t<<<(256 * 128 + 255) / 256, 256>>>(w1s, w1n, wt1, 128);
    w_to_half_t<<<(256 * 256 + 255) / 256, 256>>>(w2s, w2n, wt2, 256);

    // CSR build (per call; graph is an input)
    cudaMemsetAsync(degp, 0, (size_t)N_ * sizeof(int));
    count_kernel<<<eblocks, 256>>>(dst, E_);
    scan_block_sum<<<nb, 256>>>(N_);
    scan_block_offsets<<<1, 128>>>(nb, N_);
    scan_write<<<nb, 256>>>(N_);
    scatter_kernel<<<eblocks, 256>>>(src, dst, E_);

    // ---- layer 1 ----  (Mean(x)@W == Mean(x@W): aggregate after GEMM)
    gemm_dual_h<<<gblocks, 512>>>(xh, 128, nullptr, wt1, b1s, h1, HD, tbuf, 128, N_, 128);
    agg_bias_relu_norm<<<wblocks, 256>>>(tbuf, b1n, h1, inv1, N_);

    // ---- layer 2 ----  (L2-normalize folded into GEMM epilogue via inv1)
    gemm_dual_h<<<gblocks, 512>>>(h1, HD, inv1, wt2, b2s, h2, HD, tbuf, 128, N_, 256);
    agg_bias_relu_norm<<<wblocks, 256>>>(tbuf, b2n, h2, inv2, N_);

    // ---- head ----
    fc_kernel<<<(N_ + 63) / 64, 128>>>(h2, inv2, wfc, bfc, (float*)d_out, N_);
}

// round 6
// speedup vs baseline: 2.8963x; 1.1861x over previous
#include <cuda_runtime.h>
#include <cuda_fp16.h>
#include <cstdint>

#define NMAX 100000
#define EMAX 1600000
#define HD   256      // concat hidden dim (2*128)
#define NCLS 40
#define PAD  24       // smem row stride in halves (48B, conflict-free, 16B-aligned)
#define STAGES 3
#define FCPAD 264     // fc W smem row stride in halves

// ---------------- scratch (static device globals; no allocation) -------------
__device__ __align__(16) int g_deg[NMAX];
__device__ int   g_rowptr[NMAX + 1];
__device__ int   g_cursor[NMAX];
__device__ int   g_esrc[EMAX];
__device__ int   g_bsum[128];
__device__ int   g_boff[128];
__device__ __align__(16) __half g_t[(size_t)NMAX * 128];   // neighbor pre-agg
__device__ __align__(16) __half g_xh[(size_t)NMAX * 128];  // x in fp16
__device__ __align__(16) __half g_h1[(size_t)NMAX * HD];   // fp16 [self|neigh]
__device__ __align__(16) __half g_h2[(size_t)NMAX * HD];
__device__ __align__(16) __half g_wt1[256 * 128];          // layer1 W^T fp16 [n][k]
__device__ __align__(16) __half g_wt2[256 * 256];          // layer2 W^T fp16 [n][k]
__device__ __align__(16) __half g_wtfc[48 * 256];          // fc W^T fp16 [n][k], zero-padded
__device__ float g_inv1[NMAX];
__device__ float g_inv2[NMAX];

// ---------------- mma / cp.async helpers --------------------------------------
__device__ __forceinline__ void mma_f16(float& c0, float& c1, float& c2, float& c3,
                                        uint32_t a0, uint32_t a1, uint32_t a2, uint32_t a3,
                                        uint32_t b0, uint32_t b1) {
    asm volatile(
        "mma.sync.aligned.m16n8k16.row.col.f32.f16.f16.f32 "
        "{%0,%1,%2,%3}, {%4,%5,%6,%7}, {%8,%9}, {%0,%1,%2,%3};"
        : "+f"(c0), "+f"(c1), "+f"(c2), "+f"(c3)
        : "r"(a0), "r"(a1), "r"(a2), "r"(a3), "r"(b0), "r"(b1));
}

__device__ __forceinline__ void ldsm_x4(uint32_t* r, uint32_t addr) {
    asm volatile("ldmatrix.sync.aligned.m8n8.x4.shared.b16 {%0,%1,%2,%3}, [%4];"
                 : "=r"(r[0]), "=r"(r[1]), "=r"(r[2]), "=r"(r[3]) : "r"(addr));
}

__device__ __forceinline__ void cp_async16(uint32_t dst, const void* src, bool pred) {
    int sz = pred ? 16 : 0;
    asm volatile("cp.async.cg.shared.global [%0], [%1], 16, %2;"
                 :: "r"(dst), "l"(src), "r"(sz));
}
__device__ __forceinline__ void cp_commit() {
    asm volatile("cp.async.commit_group;" ::: "memory");
}
template <int N>
__device__ __forceinline__ void cp_wait() {
    asm volatile("cp.async.wait_group %0;" :: "n"(N) : "memory");
}

// ---------------- CSR build --------------------------------------------------
__global__ void count_kernel(const int* __restrict__ dst, int e) {
    int i = blockIdx.x * blockDim.x + threadIdx.x;
    if (i < e) atomicAdd(&g_deg[dst[i]], 1);
}

__global__ void scan_block_sum(int n) {
    int b = blockIdx.x, t = threadIdx.x, lane = t & 31, w = t >> 5;
    int base = b * 1024 + t * 4;
    int s = 0;
    if (base + 3 < n) {
        int4 v = *reinterpret_cast<const int4*>(g_deg + base);
        s = v.x + v.y + v.z + v.w;
    } else {
#pragma unroll
        for (int j = 0; j < 4; j++) { int i = base + j; if (i < n) s += g_deg[i]; }
    }
#pragma unroll
    for (int off = 16; off; off >>= 1) s += __shfl_xor_sync(0xffffffffu, s, off);
    __shared__ int ws[8];
    if (lane == 0) ws[w] = s;
    __syncthreads();
    if (t == 0) {
        int tot = 0;
#pragma unroll
        for (int j = 0; j < 8; j++) tot += ws[j];
        g_bsum[b] = tot;
    }
}

__global__ void scan_block_offsets(int nb, int n) {
    int t = threadIdx.x, lane = t & 31, w = t >> 5;
    int v = (t < nb) ? g_bsum[t] : 0;
    int val = v;
#pragma unroll
    for (int off = 1; off < 32; off <<= 1) {
        int u = __shfl_up_sync(0xffffffffu, val, off);
        if (lane >= off) val += u;
    }
    __shared__ int ws[4];
    if (lane == 31) ws[w] = val;
    __syncthreads();
    int add = 0;
#pragma unroll
    for (int j = 0; j < 4; j++) if (j < w) add += ws[j];
    int incl = val + add;
    if (t < nb) g_boff[t] = incl - v;
    if (t == nb - 1) g_rowptr[n] = incl;
}

__global__ void scan_write(int n) {
    int b = blockIdx.x, t = threadIdx.x, lane = t & 31, w = t >> 5;
    int base = b * 1024 + t * 4;
    int4 v = make_int4(0, 0, 0, 0);
    if (base + 3 < n) v = *reinterpret_cast<const int4*>(g_deg + base);
    else {
        v.x = (base < n)     ? g_deg[base]     : 0;
        v.y = (base + 1 < n) ? g_deg[base + 1] : 0;
        v.z = (base + 2 < n) ? g_deg[base + 2] : 0;
        v.w = (base + 3 < n) ? g_deg[base + 3] : 0;
    }
    int s = v.x + v.y + v.z + v.w;
    int val = s;
#pragma unroll
    for (int off = 1; off < 32; off <<= 1) {
        int u = __shfl_up_sync(0xffffffffu, val, off);
        if (lane >= off) val += u;
    }
    __shared__ int ws[8];
    if (lane == 31) ws[w] = val;
    __syncthreads();
    int wadd = 0;
#pragma unroll
    for (int j = 0; j < 8; j++) if (j < w) wadd += ws[j];
    int e0 = g_boff[b] + wadd + (val - s);
    int e1 = e0 + v.x, e2 = e1 + v.y, e3 = e2 + v.z;
    if (base < n)     { g_rowptr[base]     = e0; g_cursor[base]     = e0; }
    if (base + 1 < n) { g_rowptr[base + 1] = e1; g_cursor[base + 1] = e1; }
    if (base + 2 < n) { g_rowptr[base + 2] = e2; g_cursor[base + 2] = e2; }
    if (base + 3 < n) { g_rowptr[base + 3] = e3; g_cursor[base + 3] = e3; }
}

__global__ void scatter_kernel(const int* __restrict__ src,
                               const int* __restrict__ dst, int e) {
    int i = blockIdx.x * blockDim.x + threadIdx.x;
    if (i < e) {
        int d = dst[i];
        int pos = atomicAdd(&g_cursor[d], 1);
        g_esrc[pos] = src[i];
    }
}

// ---------------- fp16 conversions -------------------------------------------
__global__ void x_to_half(const float* __restrict__ x, __half* __restrict__ xh, int n4) {
    int i = blockIdx.x * blockDim.x + threadIdx.x;
    if (i < n4) {
        float4 v = reinterpret_cast<const float4*>(x)[i];
        __half2 p0 = __floats2half2_rn(v.x, v.y);
        __half2 p1 = __floats2half2_rn(v.z, v.w);
        uint2 u;
        u.x = *reinterpret_cast<uint32_t*>(&p0);
        u.y = *reinterpret_cast<uint32_t*>(&p1);
        reinterpret_cast<uint2*>(xh)[i] = u;
    }
}

// combined transposed weights: Wt[n][k], n<128 from W1, n>=128 from W2 (each [k][128])
__global__ void w_to_half_t(const float* __restrict__ W1, const float* __restrict__ W2,
                            __half* __restrict__ Wt, int K) {
    int idx = blockIdx.x * blockDim.x + threadIdx.x;
    if (idx < 256 * K) {
        int n = idx / K, k = idx - n * K;
        float v = (n < 128) ? W1[(size_t)k * 128 + n] : W2[(size_t)k * 128 + (n - 128)];
        Wt[idx] = __float2half_rn(v);
    }
}

// fc weights: Wt[48][256], rows 40..47 zero
__global__ void wfc_to_half_t(const float* __restrict__ W, __half* __restrict__ Wt) {
    int idx = blockIdx.x * blockDim.x + threadIdx.x;
    if (idx < 48 * 256) {
        int n = idx >> 8, k = idx & 255;
        float v = (n < NCLS) ? W[(size_t)k * NCLS + n] : 0.f;
        Wt[idx] = __float2half_rn(v);
    }
}

// ------ mean aggregation (fp16) + bias + relu + fused row L2-invnorm ---------
__device__ __forceinline__ void acc_h4(float4& a, uint2 u) {
    float2 f0 = __half22float2(*reinterpret_cast<__half2*>(&u.x));
    float2 f1 = __half22float2(*reinterpret_cast<__half2*>(&u.y));
    a.x += f0.x; a.y += f0.y; a.z += f1.x; a.w += f1.y;
}

__global__ void agg_bias_relu_norm(const __half* __restrict__ t, const float* __restrict__ bias,
                                   __half* __restrict__ h, float* __restrict__ invn, int n) {
    int gw = (blockIdx.x * blockDim.x + threadIdx.x) >> 5;
    if (gw >= n) return;
    int lane = threadIdx.x & 31;
    int beg = g_rowptr[gw], end = g_rowptr[gw + 1];
    const uint2* tb = reinterpret_cast<const uint2*>(t);
    float4 acc = make_float4(0.f, 0.f, 0.f, 0.f);
    int e = beg;
    for (; e + 4 <= end; e += 4) {
        int s0 = g_esrc[e], s1 = g_esrc[e + 1], s2 = g_esrc[e + 2], s3 = g_esrc[e + 3];
        uint2 u0 = tb[(size_t)s0 * 32 + lane];
        uint2 u1 = tb[(size_t)s1 * 32 + lane];
        uint2 u2 = tb[(size_t)s2 * 32 + lane];
        uint2 u3 = tb[(size_t)s3 * 32 + lane];
        acc_h4(acc, u0); acc_h4(acc, u1); acc_h4(acc, u2); acc_h4(acc, u3);
    }
    for (; e < end; ++e) {
        uint2 u0 = tb[(size_t)g_esrc[e] * 32 + lane];
        acc_h4(acc, u0);
    }
    int cnt = end - beg;
    float inv = 1.0f / (float)(cnt > 0 ? cnt : 1);
    float4 b = *(reinterpret_cast<const float4*>(bias) + lane);
    float4 o;
    o.x = fmaxf(acc.x * inv + b.x, 0.f);
    o.y = fmaxf(acc.y * inv + b.y, 0.f);
    o.z = fmaxf(acc.z * inv + b.z, 0.f);
    o.w = fmaxf(acc.w * inv + b.w, 0.f);
    __half* row = h + (size_t)gw * HD;
    __half2 p0 = __floats2half2_rn(o.x, o.y);
    __half2 p1 = __floats2half2_rn(o.z, o.w);
    uint2 w;
    w.x = *reinterpret_cast<uint32_t*>(&p0);
    w.y = *reinterpret_cast<uint32_t*>(&p1);
    reinterpret_cast<uint2*>(row + 128)[lane] = w;          // neigh half
    uint2 sv = reinterpret_cast<const uint2*>(row)[lane];   // self half (from GEMM)
    float2 s0 = __half22float2(*reinterpret_cast<__half2*>(&sv.x));
    float2 s1 = __half22float2(*reinterpret_cast<__half2*>(&sv.y));
    float s = s0.x * s0.x + s0.y * s0.y + s1.x * s1.x + s1.y * s1.y +
              o.x * o.x + o.y * o.y + o.z * o.z + o.w * o.w;
#pragma unroll
    for (int off = 16; off; off >>= 1) s += __shfl_xor_sync(0xffffffffu, s, off);
    if (lane == 0) invn[gw] = 1.0f / fmaxf(sqrtf(s), 1e-12f);
}

// ---- fused dual-output fp16 GEMM (3-stage cp.async + ldmatrix + m16n8k16) ----
__global__ void __launch_bounds__(512)
gemm_dual_h(const __half* __restrict__ A, int lda, const float* __restrict__ rowScale,
            const __half* __restrict__ Wt, const float* __restrict__ bias1,
            __half* __restrict__ out1, int ldo1, __half* __restrict__ out2, int ldo2,
            int M, int K) {
    __shared__ __align__(16) __half As[STAGES][128][PAD];
    __shared__ __align__(16) __half Bs[STAGES][256][PAD];

    const int t = threadIdx.x;
    const int warp = t >> 5, lane = t & 31;
    const int wm = warp & 3, wn = warp >> 2;   // 4 x 4 warp grid
    const int grp = lane >> 2, qid = lane & 3;
    const int row0 = blockIdx.x * 128;

    const uint32_t asb = (uint32_t)__cvta_generic_to_shared(&As[0][0][0]);
    const uint32_t bsb = (uint32_t)__cvta_generic_to_shared(&Bs[0][0][0]);

    float acc[2][8][4];
#pragma unroll
    for (int i = 0; i < 2; i++)
#pragma unroll
        for (int j = 0; j < 8; j++)
#pragma unroll
            for (int c = 0; c < 4; c++) acc[i][j][c] = 0.f;

    auto issue = [&](int tile, int st) {
        int k0 = tile * 16;
        if (t < 256) {
            int row = t >> 1, hf = t & 1;
            int gr = row0 + row;
            cp_async16(asb + (uint32_t)(((st * 128 + row) * PAD + hf * 8) * 2),
                       A + (size_t)gr * lda + k0 + hf * 8, gr < M);
        }
        {
            int nrow = t >> 1, hf = t & 1;
            cp_async16(bsb + (uint32_t)(((st * 256 + nrow) * PAD + hf * 8) * 2),
                       Wt + (size_t)nrow * K + k0 + hf * 8, true);
        }
        cp_commit();
    };

    const int nT = K / 16;
    issue(0, 0);
    issue(1, 1);
    cp_wait<1>();
    __syncthreads();

    for (int tile = 0; tile < nT; ++tile) {
        int cur = tile % STAGES;
        uint32_t af[2][4], bq[4][4];
#pragma unroll
        for (int mt = 0; mt < 2; ++mt) {
            int m0 = wm * 32 + mt * 16;
            int arow = m0 + (lane & 15);
            int acol = (lane >> 4) * 8;
            ldsm_x4(af[mt], asb + (uint32_t)(((cur * 128 + arow) * PAD + acol) * 2));
        }
#pragma unroll
        for (int np = 0; np < 4; ++np) {
            int n0 = wn * 64 + np * 16;
            int brow = n0 + ((lane >> 4) << 3) + (lane & 7);
            int bcol = ((lane >> 3) & 1) * 8;
            ldsm_x4(bq[np], bsb + (uint32_t)(((cur * 256 + brow) * PAD + bcol) * 2));
        }
#pragma unroll
        for (int mt = 0; mt < 2; ++mt)
#pragma unroll
            for (int nt = 0; nt < 8; ++nt)
                mma_f16(acc[mt][nt][0], acc[mt][nt][1], acc[mt][nt][2], acc[mt][nt][3],
                        af[mt][0], af[mt][1], af[mt][2], af[mt][3],
                        bq[nt >> 1][(nt & 1) * 2], bq[nt >> 1][(nt & 1) * 2 + 1]);

        if (tile + 2 < nT) {
            issue(tile + 2, (tile + 2) % STAGES);
            cp_wait<1>();
        } else {
            cp_wait<0>();
        }
        __syncthreads();
    }

#pragma unroll
    for (int mt = 0; mt < 2; ++mt) {
        int rbase = row0 + wm * 32 + mt * 16 + grp;
        float sc0 = 1.f, sc1 = 1.f;
        if (rowScale != nullptr) {
            if (rbase < M)     sc0 = rowScale[rbase];
            if (rbase + 8 < M) sc1 = rowScale[rbase + 8];
        }
#pragma unroll
        for (int nt = 0; nt < 8; ++nt) {
            int col = wn * 64 + nt * 8 + qid * 2;
            if (col < 128) {
                float b0 = bias1[col], b1 = bias1[col + 1];
                if (rbase < M) {
                    __half2 hv = __floats2half2_rn(fmaxf(acc[mt][nt][0] * sc0 + b0, 0.f),
                                                   fmaxf(acc[mt][nt][1] * sc0 + b1, 0.f));
                    *reinterpret_cast<__half2*>(out1 + (size_t)rbase * ldo1 + col) = hv;
                }
                if (rbase + 8 < M) {
                    __half2 hv = __floats2half2_rn(fmaxf(acc[mt][nt][2] * sc1 + b0, 0.f),
                                                   fmaxf(acc[mt][nt][3] * sc1 + b1, 0.f));
                    *reinterpret_cast<__half2*>(out1 + (size_t)(rbase + 8) * ldo1 + col) = hv;
                }
            } else {
                int c = col - 128;
                if (rbase < M) {
                    __half2 hv = __floats2half2_rn(acc[mt][nt][0] * sc0, acc[mt][nt][1] * sc0);
                    *reinterpret_cast<__half2*>(out2 + (size_t)rbase * ldo2 + c) = hv;
                }
                if (rbase + 8 < M) {
                    __half2 hv = __floats2half2_rn(acc[mt][nt][2] * sc1, acc[mt][nt][3] * sc1);
                    *reinterpret_cast<__half2*>(out2 + (size_t)(rbase + 8) * ldo2 + c) = hv;
                }
            }
        }
    }
}

// ---- tensor-core FC head: out[M x 40] fp32 = (A .* inv) @ Wfc + bias ---------
// A fp16 [M x 256]; Wt fp16 [48 x 256] (transposed, zero-padded); smem-resident B.
// 256 threads = 8 warps; warp w -> rows [w*16, w*16+16); 5 n-tiles of m16n8k16.
__global__ void __launch_bounds__(256)
fc_tc(const __half* __restrict__ A, const float* __restrict__ inv,
      const __half* __restrict__ Wt, const float* __restrict__ bias,
      float* __restrict__ out, int M) {
    __shared__ __align__(16) __half As[STAGES][128][PAD];
    __shared__ __align__(16) __half Bs[48][FCPAD];

    const int t = threadIdx.x;
    const int warp = t >> 5, lane = t & 31;
    const int grp = lane >> 2, qid = lane & 3;
    const int row0 = blockIdx.x * 128;

    const uint32_t asb = (uint32_t)__cvta_generic_to_shared(&As[0][0][0]);
    const uint32_t bsb = (uint32_t)__cvta_generic_to_shared(&Bs[0][0]);

    // load all of Wt into smem once (1536 uint4 chunks)
    for (int i = t; i < 1536; i += 256) {
        int r = i >> 5, c = (i & 31) << 3;
        *reinterpret_cast<uint4*>(&Bs[r][c]) =
            *reinterpret_cast<const uint4*>(Wt + (size_t)r * 256 + c);
    }

    float acc[5][4];
#pragma unroll
    for (int j = 0; j < 5; j++)
#pragma unroll
        for (int c = 0; c < 4; c++) acc[j][c] = 0.f;

    auto issueA = [&](int tile, int st) {
        int row = t >> 1, hf = t & 1;
        int gr = row0 + row;
        cp_async16(asb + (uint32_t)(((st * 128 + row) * PAD + hf * 8) * 2),
                   A + (size_t)gr * HD + tile * 16 + hf * 8, gr < M);
        cp_commit();
    };

    issueA(0, 0);
    issueA(1, 1);
    cp_wait<1>();
    __syncthreads();   // also covers the Bs fill

    const int nT = HD / 16;  // 16
    for (int tile = 0; tile < nT; ++tile) {
        int cur = tile % STAGES;
        uint32_t af[4], bq[3][4];
        {
            int arow = warp * 16 + (lane & 15);
            int acol = (lane >> 4) * 8;
            ldsm_x4(af, asb + (uint32_t)(((cur * 128 + arow) * PAD + acol) * 2));
        }
#pragma unroll
        for (int np = 0; np < 3; ++np) {
            int brow = np * 16 + ((lane >> 4) << 3) + (lane & 7);
            int bcol = tile * 16 + ((lane >> 3) & 1) * 8;
            ldsm_x4(bq[np], bsb + (uint32_t)((brow * FCPAD + bcol) * 2));
        }
#pragma unroll
        for (int nt = 0; nt < 5; ++nt)
            mma_f16(acc[nt][0], acc[nt][1], acc[nt][2], acc[nt][3],
                    af[0], af[1], af[2], af[3],
                    bq[nt >> 1][(nt & 1) * 2], bq[nt >> 1][(nt & 1) * 2 + 1]);

        if (tile + 2 < nT) {
            issueA(tile + 2, (tile + 2) % STAGES);
            cp_wait<1>();
        } else {
            cp_wait<0>();
        }
        __syncthreads();
    }

    int rbase = row0 + warp * 16 + grp;
    float sc0 = (rbase < M) ? inv[rbase] : 0.f;
    float sc1 = (rbase + 8 < M) ? inv[rbase + 8] : 0.f;
#pragma unroll
    for (int nt = 0; nt < 5; ++nt) {
        int col = nt * 8 + qid * 2;
        float b0 = bias[col], b1 = bias[col + 1];
        if (rbase < M) {
            float2 v = make_float2(acc[nt][0] * sc0 + b0, acc[nt][1] * sc0 + b1);
            *reinterpret_cast<float2*>(out + (size_t)rbase * NCLS + col) = v;
        }
        if (rbase + 8 < M) {
            float2 v = make_float2(acc[nt][2] * sc1 + b0, acc[nt][3] * sc1 + b1);
            *reinterpret_cast<float2*>(out + (size_t)(rbase + 8) * NCLS + col) = v;
        }
    }
}

// ---------------- launch ------------------------------------------------------
extern "C" void kernel_launch(void* const* d_in, const int* in_sizes, int n_in,
                              void* d_out, int out_size) {
    const float* x   = (const float*)d_in[0];
    const int*   src = (const int*)d_in[1];
    const int*   dst = (const int*)d_in[2];
    const float* w1s = (const float*)d_in[3];
    const float* b1s = (const float*)d_in[4];
    const float* w1n = (const float*)d_in[5];
    const float* b1n = (const float*)d_in[6];
    const float* w2s = (const float*)d_in[7];
    const float* b2s = (const float*)d_in[8];
    const float* w2n = (const float*)d_in[9];
    const float* b2n = (const float*)d_in[10];
    const float* wfc = (const float*)d_in[11];
    const float* bfc = (const float*)d_in[12];

    int N_ = in_sizes[0] / 128;
    int E_ = in_sizes[1];

    __half *tbuf, *xh, *h1, *h2, *wt1, *wt2, *wtfc;
    float *inv1, *inv2;
    int* degp;
    cudaGetSymbolAddress((void**)&tbuf, g_t);
    cudaGetSymbolAddress((void**)&xh, g_xh);
    cudaGetSymbolAddress((void**)&h1, g_h1);
    cudaGetSymbolAddress((void**)&h2, g_h2);
    cudaGetSymbolAddress((void**)&wt1, g_wt1);
    cudaGetSymbolAddress((void**)&wt2, g_wt2);
    cudaGetSymbolAddress((void**)&wtfc, g_wtfc);
    cudaGetSymbolAddress((void**)&inv1, g_inv1);
    cudaGetSymbolAddress((void**)&inv2, g_inv2);
    cudaGetSymbolAddress((void**)&degp, g_deg);

    // one-time side stream + events (host-side objects; created outside capture
    // on the first correctness call, reused thereafter)
    static cudaStream_t s1 = nullptr;
    static cudaEvent_t evFork = nullptr, evJoin = nullptr;
    if (s1 == nullptr) {
        cudaStreamCreateWithFlags(&s1, cudaStreamNonBlocking);
        cudaEventCreateWithFlags(&evFork, cudaEventDisableTiming);
        cudaEventCreateWithFlags(&evJoin, cudaEventDisableTiming);
    }

    int eblocks = (E_ + 255) / 256;
    int wblocks = (N_ * 32 + 255) / 256;   // warp-per-node kernels
    int gblocks = (N_ + 127) / 128;        // gemm row tiles
    int nb = (N_ + 1023) / 1024;           // scan chunks

    // ---- fork: CSR build on side stream, overlapped with conv + GEMM1 ----
    cudaEventRecord(evFork, 0);
    cudaStreamWaitEvent(s1, evFork, 0);
    cudaMemsetAsync(degp, 0, (size_t)N_ * sizeof(int), s1);
    count_kernel<<<eblocks, 256, 0, s1>>>(dst, E_);
    scan_block_sum<<<nb, 256, 0, s1>>>(N_);
    scan_block_offsets<<<1, 128, 0, s1>>>(nb, N_);
    scan_write<<<nb, 256, 0, s1>>>(N_);
    scatter_kernel<<<eblocks, 256, 0, s1>>>(src, dst, E_);
    cudaEventRecord(evJoin, s1);

    // ---- main stream: conversions + layer-1 GEMM (independent of CSR) ----
    x_to_half<<<(N_ * 32 + 255) / 256, 256>>>(x, xh, N_ * 32);
    w_to_half_t<<<(256 * 128 + 255) / 256, 256>>>(w1s, w1n, wt1, 128);
    w_to_half_t<<<(256 * 256 + 255) / 256, 256>>>(w2s, w2n, wt2, 256);
    wfc_to_half_t<<<(48 * 256 + 255) / 256, 256>>>(wfc, wtfc);
    gemm_dual_h<<<gblocks, 512>>>(xh, 128, nullptr, wt1, b1s, h1, HD, tbuf, 128, N_, 128);

    // ---- join: aggregation needs the CSR ----
    cudaStreamWaitEvent(0, evJoin, 0);
    agg_bias_relu_norm<<<wblocks, 256>>>(tbuf, b1n, h1, inv1, N_);

    // ---- layer 2 ----
    gemm_dual_h<<<gblocks, 512>>>(h1, HD, inv1, wt2, b2s, h2, HD, tbuf, 128, N_, 256);
    agg_bias_relu_norm<<<wblocks, 256>>>(tbuf, b2n, h2, inv2, N_);

    // ---- head (tensor-core) ----
    fc_tc<<<gblocks, 256>>>(h2, inv2, wtfc, bfc, (float*)d_out, N_);
}